// round 8
// baseline (speedup 1.0000x reference)
#include <cuda_runtime.h>
#include <cuda_bf16.h>
#include <cstdint>
#include <math.h>

// ---------------- problem shape ----------------------------------------------
#define B_   2
#define S_   2048
#define D_   1024
#define H_   16
#define HD   64
#define MTOT (B_*S_)          // 4096
#define SCALE 0.125f          // 1/sqrt(64), exact power of two

// ---------------- baseline-PTX helpers (compile at compute_103) --------------
__device__ __forceinline__ uint32_t smem_u32(const void* p) {
    uint32_t a;
    asm("{ .reg .u64 t; cvta.to.shared.u64 t, %1; cvt.u32.u64 %0, t; }"
        : "=r"(a) : "l"(p));
    return a;
}
#define CP_ASYNC16(dst, src) \
    asm volatile("cp.async.cg.shared.global [%0], [%1], 16;" :: "r"(dst), "l"(src))
#define CP_COMMIT() asm volatile("cp.async.commit_group;" ::: "memory")
#define CP_WAIT2()  asm volatile("cp.async.wait_group 2;" ::: "memory")
#define CP_WAIT1()  asm volatile("cp.async.wait_group 1;" ::: "memory")
#define CP_WAIT0()  asm volatile("cp.async.wait_group 0;" ::: "memory")

__device__ __forceinline__ void ldsm4(uint32_t& r0, uint32_t& r1,
                                      uint32_t& r2, uint32_t& r3, uint32_t a) {
    asm volatile("ldmatrix.sync.aligned.m8n8.x4.shared.b16 {%0,%1,%2,%3}, [%4];"
                 : "=r"(r0), "=r"(r1), "=r"(r2), "=r"(r3) : "r"(a));
}
__device__ __forceinline__ void ldsm4t(uint32_t& r0, uint32_t& r1,
                                       uint32_t& r2, uint32_t& r3, uint32_t a) {
    asm volatile("ldmatrix.sync.aligned.m8n8.x4.trans.shared.b16 {%0,%1,%2,%3}, [%4];"
                 : "=r"(r0), "=r"(r1), "=r"(r2), "=r"(r3) : "r"(a));
}
__device__ __forceinline__ void mma_bf16(float* c,
    uint32_t a0, uint32_t a1, uint32_t a2, uint32_t a3, uint32_t b0, uint32_t b1) {
    asm volatile("mma.sync.aligned.m16n8k16.row.col.f32.bf16.bf16.f32 "
                 "{%0,%1,%2,%3}, {%4,%5,%6,%7}, {%8,%9}, {%0,%1,%2,%3};"
                 : "+f"(c[0]), "+f"(c[1]), "+f"(c[2]), "+f"(c[3])
                 : "r"(a0), "r"(a1), "r"(a2), "r"(a3), "r"(b0), "r"(b1));
}
__device__ __forceinline__ uint32_t pack_bf2(float lo, float hi) {
    __nv_bfloat162 t = __floats2bfloat162_rn(lo, hi);
    return *(uint32_t*)&t;
}

// ---------------- scratch (device globals; no allocations allowed) ----------
__device__ __nv_bfloat16 g_qh[(size_t)B_*H_*S_*HD], g_ql[(size_t)B_*H_*S_*HD];
__device__ __nv_bfloat16 g_kh[(size_t)B_*H_*S_*HD], g_kl[(size_t)B_*H_*S_*HD];
__device__ __nv_bfloat16 g_vh[(size_t)B_*H_*S_*HD], g_vl[(size_t)B_*H_*S_*HD];
__device__ __nv_bfloat16 g_xh[(size_t)MTOT*D_],  g_xl[(size_t)MTOT*D_];
__device__ __nv_bfloat16 g_wh[(size_t)4*D_*D_],  g_wl[(size_t)4*D_*D_];
__device__ __nv_bfloat16 g_ath[(size_t)MTOT*D_], g_atl[(size_t)MTOT*D_];
__device__ float2 g_rope[(size_t)S_*32];          // (cos,sin) per (spos, d/2)

// ---------------- RoPE table (exact sincosf, one-time) -----------------------
__global__ void rope_kernel(float2* __restrict__ t)
{
    int i = blockIdx.x * blockDim.x + threadIdx.x;    // over S_*32
    if (i >= S_ * 32) return;
    int spos = i >> 5, d2 = i & 31;
    float theta = powf(10000.0f, -2.0f * (float)d2 / (float)HD);
    float ang = (float)spos * theta;
    float ss, cc;
    sincosf(ang, &ss, &cc);
    t[i] = make_float2(cc, ss);
}

// ---------------- fused fp32 -> (bf16 hi, bf16 lo) split for x + 4 W ---------
#define RW  ((D_*D_)/4)        // 262144 float4 per weight
__global__ void split_all(const float* __restrict__ x,
                          const float* __restrict__ w0, const float* __restrict__ w1,
                          const float* __restrict__ w2, const float* __restrict__ w3,
                          __nv_bfloat16* __restrict__ xh, __nv_bfloat16* __restrict__ xl,
                          __nv_bfloat16* __restrict__ wh, __nv_bfloat16* __restrict__ wl)
{
    int i = blockIdx.x * blockDim.x + threadIdx.x;    // float4 index, 8*RW total
    const float* src;
    __nv_bfloat16 *hi, *lo;
    int local;
    if (i < 4 * RW) {
        src = x; hi = xh; lo = xl; local = i;
    } else {
        int ip = i - 4 * RW;
        int r  = ip >> 18;     // RW = 2^18
        local  = ip & (RW - 1);
        src = (r == 0) ? w0 : (r == 1) ? w1 : (r == 2) ? w2 : w3;
        hi = wh + (size_t)r * D_ * D_;
        lo = wl + (size_t)r * D_ * D_;
    }
    float4 v = ((const float4*)src)[local];
    __nv_bfloat16 h0 = __float2bfloat16(v.x);
    __nv_bfloat16 h1 = __float2bfloat16(v.y);
    __nv_bfloat16 h2 = __float2bfloat16(v.z);
    __nv_bfloat16 h3 = __float2bfloat16(v.w);
    __nv_bfloat16 l0 = __float2bfloat16(v.x - __bfloat162float(h0));
    __nv_bfloat16 l1 = __float2bfloat16(v.y - __bfloat162float(h1));
    __nv_bfloat16 l2 = __float2bfloat16(v.z - __bfloat162float(h2));
    __nv_bfloat16 l3 = __float2bfloat16(v.w - __bfloat162float(h3));
    __nv_bfloat162 a, b;
    a.x = h0; a.y = h1; b.x = h2; b.y = h3;
    ((__nv_bfloat162*)hi)[2*local]   = a;
    ((__nv_bfloat162*)hi)[2*local+1] = b;
    a.x = l0; a.y = l1; b.x = l2; b.y = l3;
    ((__nv_bfloat162*)lo)[2*local]   = a;
    ((__nv_bfloat162*)lo)[2*local+1] = b;
}

// ---------------- HMMA GEMM (3-stage): C[m,n] = sum_k A[m,k]*W[n,k] ----------
#define BKG 32
#define NKI (D_/BKG)       // 32
#define STG 32768          // bytes per stage
#define GSMEM (3*STG)      // 96 KB

__device__ __forceinline__ uint32_t sw_off(int row, int kc) {
    return (uint32_t)((row << 6) + ((kc ^ ((row >> 1) & 3)) << 4));
}

__device__ __forceinline__ void stage_load(
    uint32_t sb, int s, int k0, int tid, int m0, int n0,
    const __nv_bfloat16* __restrict__ Ah, const __nv_bfloat16* __restrict__ Al,
    const __nv_bfloat16* __restrict__ Bh, const __nv_bfloat16* __restrict__ Bl)
{
    const uint32_t base = sb + (uint32_t)s * STG;
#pragma unroll
    for (int p = 0; p < 2; p++) {
        const int gi  = tid + p * 256;
        const int row = gi >> 2;
        const int kc  = gi & 3;
        const uint32_t so = sw_off(row, kc);
        const size_t aoff = (size_t)(m0 + row) * D_ + k0 + kc * 8;
        const size_t boff = (size_t)(n0 + row) * D_ + k0 + kc * 8;
        CP_ASYNC16(base + 0     + so, Ah + aoff);
        CP_ASYNC16(base + 8192  + so, Al + aoff);
        CP_ASYNC16(base + 16384 + so, Bh + boff);
        CP_ASYNC16(base + 24576 + so, Bl + boff);
    }
}

// QKV=1: n0 in [0,3072): B = Wq|Wk|Wv rows; RoPE/scale + bf16 hi/lo scatter.
// QKV=0: n0 in [0,1024): B = Wo rows; fp32 [M,D] output.
template<int QKV>
__global__ __launch_bounds__(256, 1)
void gemm_mma(const __nv_bfloat16* __restrict__ Ah, const __nv_bfloat16* __restrict__ Al,
              const __nv_bfloat16* __restrict__ Bh, const __nv_bfloat16* __restrict__ Bl,
              float* __restrict__ Cf,
              __nv_bfloat16* __restrict__ Qh, __nv_bfloat16* __restrict__ Ql,
              __nv_bfloat16* __restrict__ Kh, __nv_bfloat16* __restrict__ Kl,
              __nv_bfloat16* __restrict__ Vh, __nv_bfloat16* __restrict__ Vl)
{
    extern __shared__ char smem[];
    const uint32_t sb = smem_u32(smem);
    const int tid  = threadIdx.x;
    const int wid  = tid >> 5;
    const int lane = tid & 31;
    const int m0 = blockIdx.y * 128;
    const int n0 = blockIdx.x * 128;
    const int wm = (wid & 1) * 64;
    const int wn = (wid >> 1) * 32;

    float acc[4][4][4];
#pragma unroll
    for (int a = 0; a < 4; a++)
#pragma unroll
        for (int b = 0; b < 4; b++)
#pragma unroll
            for (int c = 0; c < 4; c++) acc[a][b][c] = 0.f;

    stage_load(sb, 0, 0, tid, m0, n0, Ah, Al, Bh, Bl);
    CP_COMMIT();
    stage_load(sb, 1, BKG, tid, m0, n0, Ah, Al, Bh, Bl);
    CP_COMMIT();

    const int g = lane >> 3;
    const int r = lane & 7;

    for (int i = 0; i < NKI; i++) {
        if (i + 2 < NKI) {
            int s = i + 2; while (s >= 3) s -= 3;
            stage_load(sb, s, (i + 2) * BKG, tid, m0, n0, Ah, Al, Bh, Bl);
            CP_COMMIT();
            CP_WAIT2();
        } else if (i + 1 < NKI) {
            CP_WAIT1();
        } else {
            CP_WAIT0();
        }
        __syncthreads();     // cross-thread visibility of stage i's cp.asyncs
        int cs = i; while (cs >= 3) cs -= 3;
        const uint32_t base = sb + (uint32_t)cs * STG;
#pragma unroll
        for (int h = 0; h < 2; h++) {
            uint32_t ah[4][4], al[4][4], bhf[2][4], blf[2][4];
#pragma unroll
            for (int mi = 0; mi < 4; mi++) {
                const int arow = wm + mi * 16 + (g & 1) * 8 + r;
                const int akc  = h * 2 + (g >> 1);
                const uint32_t so = sw_off(arow, akc);
                ldsm4(ah[mi][0], ah[mi][1], ah[mi][2], ah[mi][3], base + 0 + so);
                ldsm4(al[mi][0], al[mi][1], al[mi][2], al[mi][3], base + 8192 + so);
            }
#pragma unroll
            for (int ng = 0; ng < 2; ng++) {
                const int brow = wn + ng * 16 + (g >> 1) * 8 + r;
                const int bkc  = h * 2 + (g & 1);
                const uint32_t so = sw_off(brow, bkc);
                ldsm4(bhf[ng][0], bhf[ng][1], bhf[ng][2], bhf[ng][3], base + 16384 + so);
                ldsm4(blf[ng][0], blf[ng][1], blf[ng][2], blf[ng][3], base + 24576 + so);
            }
#pragma unroll
            for (int mi = 0; mi < 4; mi++)
#pragma unroll
                for (int ni = 0; ni < 4; ni++) {
                    const uint32_t* bh = &bhf[ni >> 1][(ni & 1) * 2];
                    const uint32_t* bl = &blf[ni >> 1][(ni & 1) * 2];
                    mma_bf16(acc[mi][ni], ah[mi][0], ah[mi][1], ah[mi][2], ah[mi][3], bh[0], bh[1]);
                    mma_bf16(acc[mi][ni], ah[mi][0], ah[mi][1], ah[mi][2], ah[mi][3], bl[0], bl[1]);
                    mma_bf16(acc[mi][ni], al[mi][0], al[mi][1], al[mi][2], al[mi][3], bh[0], bh[1]);
                }
        }
        __syncthreads();     // all reads of this stage done before it is refilled
    }

    // ---------------- epilogue ------------------------------------------------
    const int w = QKV ? (n0 >> 10) : 3;
    const int tg = lane >> 2;
    const int tq = lane & 3;
#pragma unroll
    for (int mi = 0; mi < 4; mi++) {
#pragma unroll
        for (int hf = 0; hf < 2; hf++) {
            const int m    = m0 + wm + mi * 16 + hf * 8 + tg;
            const int spos = m & (S_ - 1);
            const int bb   = m >> 11;
#pragma unroll
            for (int ni = 0; ni < 4; ni++) {
                const int n = n0 + wn + ni * 8 + tq * 2;     // even (global)
                float v1 = acc[mi][ni][hf * 2 + 0];
                float v2 = acc[mi][ni][hf * 2 + 1];
                if (QKV) {
                    const int nl = n & 1023;
                    const int d  = nl & (HD - 1);
                    if (w < 2) {
                        float2 cs = g_rope[spos * 32 + (d >> 1)];
                        float y1 = v1 * cs.x - v2 * cs.y;
                        float y2 = v1 * cs.y + v2 * cs.x;
                        v1 = y1; v2 = y2;
                    }
                    if (w == 0) { v1 *= SCALE; v2 *= SCALE; }
                    const int hh = nl >> 6;
                    const size_t idx = (((size_t)(bb * H_ + hh) * S_) + spos) * HD + d;
                    __nv_bfloat16 h1 = __float2bfloat16(v1);
                    __nv_bfloat16 h2 = __float2bfloat16(v2);
                    __nv_bfloat16 l1 = __float2bfloat16(v1 - __bfloat162float(h1));
                    __nv_bfloat16 l2 = __float2bfloat16(v2 - __bfloat162float(h2));
                    __nv_bfloat162 hp; hp.x = h1; hp.y = h2;
                    __nv_bfloat162 lp; lp.x = l1; lp.y = l2;
                    __nv_bfloat16* Ch = (w == 0) ? Qh : (w == 1) ? Kh : Vh;
                    __nv_bfloat16* Cl = (w == 0) ? Ql : (w == 1) ? Kl : Vl;
                    *(__nv_bfloat162*)(Ch + idx) = hp;
                    *(__nv_bfloat162*)(Cl + idx) = lp;
                } else {
                    float* p = Cf + (size_t)m * D_ + n;
                    *(float2*)p = make_float2(v1, v2);
                }
            }
        }
    }
}

// ---------------- HMMA flash attention (causal) ------------------------------
// 128 threads (4 warps), Q tile 64 rows (16/warp), K/V tiles 64 rows,
// double-buffered cp.async. Q is STAGED THROUGH the stage-0 K/V buffer at
// prologue (read once, lives in registers) -> smem = 64KB total, and with
// __launch_bounds__(128,3) -> 3 CTAs/SM (12 warps) for tensor-pipe overlap.
#define FSTG    32768u
#define FSMEM   (2*32768)

__device__ __forceinline__ uint32_t fsw(int row, int c) {   // 128B rows
    return (uint32_t)(row * 128 + ((c ^ (row & 7)) << 4));
}

__device__ __forceinline__ void fa_stage(
    uint32_t base, const __nv_bfloat16* kh, const __nv_bfloat16* kl,
    const __nv_bfloat16* vh, const __nv_bfloat16* vl, int s0, int tid)
{
#pragma unroll
    for (int p = 0; p < 4; p++) {
        const int gi  = tid + p * 128;       // 0..511
        const int row = gi >> 3;
        const int c   = gi & 7;
        const uint32_t off = fsw(row, c);
        const size_t g = (size_t)(s0 + row) * HD + c * 8;
        CP_ASYNC16(base + 0u     + off, kh + g);
        CP_ASYNC16(base + 8192u  + off, kl + g);
        CP_ASYNC16(base + 16384u + off, vh + g);
        CP_ASYNC16(base + 24576u + off, vl + g);
    }
}

__global__ __launch_bounds__(128, 3)
void flash_mma(const __nv_bfloat16* __restrict__ Qh, const __nv_bfloat16* __restrict__ Ql,
               const __nv_bfloat16* __restrict__ Kh, const __nv_bfloat16* __restrict__ Kl,
               const __nv_bfloat16* __restrict__ Vh, const __nv_bfloat16* __restrict__ Vl,
               __nv_bfloat16* __restrict__ Oh, __nv_bfloat16* __restrict__ Ol)
{
    extern __shared__ char smem[];
    const uint32_t sb = smem_u32(smem);
    const int tid  = threadIdx.x;
    const int wid  = tid >> 5;
    const int lane = tid & 31;
    const int bh = blockIdx.y;
    const int mt = (int)gridDim.x - 1 - (int)blockIdx.x;   // big tiles first
    const int nkt = mt + 1;                                // 64-row K tiles

    const __nv_bfloat16* qhb = Qh + ((size_t)bh * S_) * HD;
    const __nv_bfloat16* qlb = Ql + ((size_t)bh * S_) * HD;
    const __nv_bfloat16* khb_ = Kh + ((size_t)bh * S_) * HD;
    const __nv_bfloat16* klb_ = Kl + ((size_t)bh * S_) * HD;
    const __nv_bfloat16* vhb_ = Vh + ((size_t)bh * S_) * HD;
    const __nv_bfloat16* vlb_ = Vl + ((size_t)bh * S_) * HD;

    const int grp = lane >> 3;
    const int rr  = lane & 7;

    // ---- stage Q through stage-0 buffer, extract frags to registers --------
#pragma unroll
    for (int p = 0; p < 4; p++) {
        const int gi  = tid + p * 128;       // 0..511
        const int row = gi >> 3;
        const int c   = gi & 7;
        const uint32_t off = fsw(row, c);
        const size_t g = (size_t)(mt * 64 + row) * HD + c * 8;
        CP_ASYNC16(sb + 0u    + off, qhb + g);
        CP_ASYNC16(sb + 8192u + off, qlb + g);
    }
    CP_COMMIT();
    CP_WAIT0();
    __syncthreads();

    uint32_t qhf[4][4], qlf[4][4];
#pragma unroll
    for (int kc = 0; kc < 4; kc++) {
        const int row = wid * 16 + (grp & 1) * 8 + rr;
        const int c   = kc * 2 + (grp >> 1);
        const uint32_t off = fsw(row, c);
        ldsm4(qhf[kc][0], qhf[kc][1], qhf[kc][2], qhf[kc][3], sb + 0u + off);
        ldsm4(qlf[kc][0], qlf[kc][1], qlf[kc][2], qlf[kc][3], sb + 8192u + off);
    }
    __syncthreads();     // Q frags extracted before stage-0 is overwritten

    fa_stage(sb, khb_, klb_, vhb_, vlb_, 0, tid);
    CP_COMMIT();

    float o[8][4];
#pragma unroll
    for (int a = 0; a < 8; a++)
#pragma unroll
        for (int b = 0; b < 4; b++) o[a][b] = 0.f;
    float m0r = -1e30f, m1r = -1e30f, l0r = 0.f, l1r = 0.f;

    for (int kt = 0; kt < nkt; kt++) {
        if (kt + 1 < nkt) {
            fa_stage(sb + (uint32_t)((kt + 1) & 1) * FSTG,
                     khb_, klb_, vhb_, vlb_, (kt + 1) * 64, tid);
            CP_COMMIT();
            CP_WAIT1();
        } else {
            CP_WAIT0();
        }
        __syncthreads();     // stage kt visible to all threads

        const uint32_t st = sb + (uint32_t)(kt & 1) * FSTG;

        // ---- scores S = Q K^T --------------------------------------------
        float c[8][4];
#pragma unroll
        for (int a = 0; a < 8; a++)
#pragma unroll
            for (int b = 0; b < 4; b++) c[a][b] = 0.f;

#pragma unroll
        for (int nt = 0; nt < 8; nt++) {
            const int j = nt * 8 + rr;
            uint32_t kb0[4], kb1[4], lb0[4], lb1[4];
            ldsm4(kb0[0], kb0[1], kb0[2], kb0[3], st + 0u    + fsw(j, 0 + grp));
            ldsm4(kb1[0], kb1[1], kb1[2], kb1[3], st + 0u    + fsw(j, 4 + grp));
            ldsm4(lb0[0], lb0[1], lb0[2], lb0[3], st + 8192u + fsw(j, 0 + grp));
            ldsm4(lb1[0], lb1[1], lb1[2], lb1[3], st + 8192u + fsw(j, 4 + grp));
            mma_bf16(c[nt], qhf[0][0], qhf[0][1], qhf[0][2], qhf[0][3], kb0[0], kb0[1]);
            mma_bf16(c[nt], qhf[0][0], qhf[0][1], qhf[0][2], qhf[0][3], lb0[0], lb0[1]);
            mma_bf16(c[nt], qlf[0][0], qlf[0][1], qlf[0][2], qlf[0][3], kb0[0], kb0[1]);
            mma_bf16(c[nt], qhf[1][0], qhf[1][1], qhf[1][2], qhf[1][3], kb0[2], kb0[3]);
            mma_bf16(c[nt], qhf[1][0], qhf[1][1], qhf[1][2], qhf[1][3], lb0[2], lb0[3]);
            mma_bf16(c[nt], qlf[1][0], qlf[1][1], qlf[1][2], qlf[1][3], kb0[2], kb0[3]);
            mma_bf16(c[nt], qhf[2][0], qhf[2][1], qhf[2][2], qhf[2][3], kb1[0], kb1[1]);
            mma_bf16(c[nt], qhf[2][0], qhf[2][1], qhf[2][2], qhf[2][3], lb1[0], lb1[1]);
            mma_bf16(c[nt], qlf[2][0], qlf[2][1], qlf[2][2], qlf[2][3], kb1[0], kb1[1]);
            mma_bf16(c[nt], qhf[3][0], qhf[3][1], qhf[3][2], qhf[3][3], kb1[2], kb1[3]);
            mma_bf16(c[nt], qhf[3][0], qhf[3][1], qhf[3][2], qhf[3][3], lb1[2], lb1[3]);
            mma_bf16(c[nt], qlf[3][0], qlf[3][1], qlf[3][2], qlf[3][3], kb1[2], kb1[3]);
        }

        // ---- causal mask on diagonal tile --------------------------------
        if (kt == mt) {
            const int i0 = wid * 16 + (lane >> 2);
#pragma unroll
            for (int nt = 0; nt < 8; nt++) {
                const int j0 = nt * 8 + (lane & 3) * 2;
                if (j0     > i0)     c[nt][0] = -1e30f;
                if (j0 + 1 > i0)     c[nt][1] = -1e30f;
                if (j0     > i0 + 8) c[nt][2] = -1e30f;
                if (j0 + 1 > i0 + 8) c[nt][3] = -1e30f;
            }
        }

        // ---- online softmax ----------------------------------------------
        float t0 = -1e30f, t1 = -1e30f;
#pragma unroll
        for (int nt = 0; nt < 8; nt++) {
            t0 = fmaxf(t0, fmaxf(c[nt][0], c[nt][1]));
            t1 = fmaxf(t1, fmaxf(c[nt][2], c[nt][3]));
        }
        t0 = fmaxf(t0, __shfl_xor_sync(0xffffffffu, t0, 1));
        t0 = fmaxf(t0, __shfl_xor_sync(0xffffffffu, t0, 2));
        t1 = fmaxf(t1, __shfl_xor_sync(0xffffffffu, t1, 1));
        t1 = fmaxf(t1, __shfl_xor_sync(0xffffffffu, t1, 2));
        const float mn0 = fmaxf(m0r, t0);
        const float mn1 = fmaxf(m1r, t1);
        const float al0 = __expf(m0r - mn0);
        const float al1 = __expf(m1r - mn1);
        m0r = mn0; m1r = mn1;

        float s0 = 0.f, s1 = 0.f;
#pragma unroll
        for (int nt = 0; nt < 8; nt++) {
            c[nt][0] = __expf(c[nt][0] - mn0);
            c[nt][1] = __expf(c[nt][1] - mn0);
            c[nt][2] = __expf(c[nt][2] - mn1);
            c[nt][3] = __expf(c[nt][3] - mn1);
            s0 += c[nt][0] + c[nt][1];
            s1 += c[nt][2] + c[nt][3];
        }
        s0 += __shfl_xor_sync(0xffffffffu, s0, 1);
        s0 += __shfl_xor_sync(0xffffffffu, s0, 2);
        s1 += __shfl_xor_sync(0xffffffffu, s1, 1);
        s1 += __shfl_xor_sync(0xffffffffu, s1, 2);
        l0r = l0r * al0 + s0;
        l1r = l1r * al1 + s1;

#pragma unroll
        for (int nt = 0; nt < 8; nt++) {
            o[nt][0] *= al0; o[nt][1] *= al0;
            o[nt][2] *= al1; o[nt][3] *= al1;
        }

        // ---- O += P V, P converted per-kc (low register pressure) --------
#pragma unroll
        for (int kc = 0; kc < 4; kc++) {
            uint32_t ph[4], pl[4];
            const float* p0 = c[2*kc];
            const float* p1 = c[2*kc+1];
            ph[0] = pack_bf2(p0[0], p0[1]);
            ph[1] = pack_bf2(p0[2], p0[3]);
            ph[2] = pack_bf2(p1[0], p1[1]);
            ph[3] = pack_bf2(p1[2], p1[3]);
            __nv_bfloat162 hh;
            *(uint32_t*)&hh = ph[0];
            pl[0] = pack_bf2(p0[0]-__bfloat162float(hh.x), p0[1]-__bfloat162float(hh.y));
            *(uint32_t*)&hh = ph[1];
            pl[1] = pack_bf2(p0[2]-__bfloat162float(hh.x), p0[3]-__bfloat162float(hh.y));
            *(uint32_t*)&hh = ph[2];
            pl[2] = pack_bf2(p1[0]-__bfloat162float(hh.x), p1[1]-__bfloat162float(hh.y));
            *(uint32_t*)&hh = ph[3];
            pl[3] = pack_bf2(p1[2]-__bfloat162float(hh.x), p1[3]-__bfloat162float(hh.y));
#pragma unroll
            for (int ntp = 0; ntp < 4; ntp++) {
                const int row = kc * 16 + (grp & 1) * 8 + rr;
                const int ch  = ntp * 2 + (grp >> 1);
                const uint32_t off = fsw(row, ch);
                uint32_t vh0, vh1, vh2, vh3, vl0, vl1, vl2, vl3;
                ldsm4t(vh0, vh1, vh2, vh3, st + 16384u + off);
                ldsm4t(vl0, vl1, vl2, vl3, st + 24576u + off);
                mma_bf16(o[2*ntp],   ph[0], ph[1], ph[2], ph[3], vh0, vh1);
                mma_bf16(o[2*ntp],   ph[0], ph[1], ph[2], ph[3], vl0, vl1);
                mma_bf16(o[2*ntp],   pl[0], pl[1], pl[2], pl[3], vh0, vh1);
                mma_bf16(o[2*ntp+1], ph[0], ph[1], ph[2], ph[3], vh2, vh3);
                mma_bf16(o[2*ntp+1], ph[0], ph[1], ph[2], ph[3], vl2, vl3);
                mma_bf16(o[2*ntp+1], pl[0], pl[1], pl[2], pl[3], vh2, vh3);
            }
        }
        __syncthreads();     // all reads of this buffer done before refill
    }

    // ---- finalize + write bf16 hi/lo [B,S,D] --------------------------------
    const float inv0 = 1.f / l0r;
    const float inv1 = 1.f / l1r;
    const int b = bh >> 4;
    const int h = bh & (H_ - 1);
    const int sq0 = mt * 64 + wid * 16 + (lane >> 2);
    const size_t base0 = ((size_t)(b * S_ + sq0)) * D_ + h * HD;
    const size_t base1 = base0 + (size_t)8 * D_;
#pragma unroll
    for (int nt = 0; nt < 8; nt++) {
        const int col = nt * 8 + (lane & 3) * 2;
        {
            float v0 = o[nt][0] * inv0, v1 = o[nt][1] * inv0;
            __nv_bfloat16 h0 = __float2bfloat16(v0);
            __nv_bfloat16 h1 = __float2bfloat16(v1);
            __nv_bfloat16 l0 = __float2bfloat16(v0 - __bfloat162float(h0));
            __nv_bfloat16 l1 = __float2bfloat16(v1 - __bfloat162float(h1));
            __nv_bfloat162 hp; hp.x = h0; hp.y = h1;
            __nv_bfloat162 lp; lp.x = l0; lp.y = l1;
            *(__nv_bfloat162*)(Oh + base0 + col) = hp;
            *(__nv_bfloat162*)(Ol + base0 + col) = lp;
        }
        {
            float v0 = o[nt][2] * inv1, v1 = o[nt][3] * inv1;
            __nv_bfloat16 h0 = __float2bfloat16(v0);
            __nv_bfloat16 h1 = __float2bfloat16(v1);
            __nv_bfloat16 l0 = __float2bfloat16(v0 - __bfloat162float(h0));
            __nv_bfloat16 l1 = __float2bfloat16(v1 - __bfloat162float(h1));
            __nv_bfloat162 hp; hp.x = h0; hp.y = h1;
            __nv_bfloat162 lp; lp.x = l0; lp.y = l1;
            *(__nv_bfloat162*)(Oh + base1 + col) = hp;
            *(__nv_bfloat162*)(Ol + base1 + col) = lp;
        }
    }
}

// ---------------- launch -----------------------------------------------------
extern "C" void kernel_launch(void* const* d_in, const int* in_sizes, int n_in,
                              void* d_out, int out_size)
{
    const float* x  = (const float*)d_in[0];
    float* out = (float*)d_out;

    void *pqh, *pql, *pkh, *pkl, *pvh, *pvl, *pxh, *pxl, *pwh, *pwl, *path, *patl, *prope;
    cudaGetSymbolAddress(&pqh, g_qh);  cudaGetSymbolAddress(&pql, g_ql);
    cudaGetSymbolAddress(&pkh, g_kh);  cudaGetSymbolAddress(&pkl, g_kl);
    cudaGetSymbolAddress(&pvh, g_vh);  cudaGetSymbolAddress(&pvl, g_vl);
    cudaGetSymbolAddress(&pxh, g_xh);  cudaGetSymbolAddress(&pxl, g_xl);
    cudaGetSymbolAddress(&pwh, g_wh);  cudaGetSymbolAddress(&pwl, g_wl);
    cudaGetSymbolAddress(&path, g_ath); cudaGetSymbolAddress(&patl, g_atl);
    cudaGetSymbolAddress(&prope, g_rope);

    cudaFuncSetAttribute(gemm_mma<1>, cudaFuncAttributeMaxDynamicSharedMemorySize, GSMEM);
    cudaFuncSetAttribute(gemm_mma<0>, cudaFuncAttributeMaxDynamicSharedMemorySize, GSMEM);
    cudaFuncSetAttribute(flash_mma, cudaFuncAttributeMaxDynamicSharedMemorySize, FSMEM);

    __nv_bfloat16* xh = (__nv_bfloat16*)pxh;
    __nv_bfloat16* xl = (__nv_bfloat16*)pxl;
    __nv_bfloat16* wh = (__nv_bfloat16*)pwh;
    __nv_bfloat16* wl = (__nv_bfloat16*)pwl;

    // RoPE table + fused splits
    rope_kernel<<<(S_ * 32 + 255) / 256, 256>>>((float2*)prope);
    split_all<<<(8 * RW) / 256, 256>>>(x, (const float*)d_in[1], (const float*)d_in[2],
                                       (const float*)d_in[3], (const float*)d_in[4],
                                       xh, xl, wh, wl);

    // fused QKV projection (RoPE/scale in epilogue) -> bf16 hi/lo [B,H,S,hd]
    dim3 qkvgrid(3 * D_ / 128, MTOT / 128);   // (24, 32)
    gemm_mma<1><<<qkvgrid, 256, GSMEM>>>(xh, xl, wh, wl, nullptr,
        (__nv_bfloat16*)pqh, (__nv_bfloat16*)pql,
        (__nv_bfloat16*)pkh, (__nv_bfloat16*)pkl,
        (__nv_bfloat16*)pvh, (__nv_bfloat16*)pvl);

    // tensor-core causal flash attention -> bf16 hi/lo [B,S,D]
    dim3 agrid(S_ / 64, B_ * H_);        // (32, 32) = 1024 CTAs, 3/SM
    flash_mma<<<agrid, 128, FSMEM>>>((const __nv_bfloat16*)pqh, (const __nv_bfloat16*)pql,
                                     (const __nv_bfloat16*)pkh, (const __nv_bfloat16*)pkl,
                                     (const __nv_bfloat16*)pvh, (const __nv_bfloat16*)pvl,
                                     (__nv_bfloat16*)path, (__nv_bfloat16*)patl);

    // output projection -> d_out (fp32)
    dim3 ogrid(D_ / 128, MTOT / 128);    // (8, 32)
    gemm_mma<0><<<ogrid, 256, GSMEM>>>((const __nv_bfloat16*)path, (const __nv_bfloat16*)patl,
                                       wh + 3*(size_t)D_*D_, wl + 3*(size_t)D_*D_,
                                       out, nullptr, nullptr, nullptr, nullptr, nullptr, nullptr);
}

// round 9
// speedup vs baseline: 1.1460x; 1.1460x over previous
#include <cuda_runtime.h>
#include <cuda_fp16.h>
#include <cstdint>
#include <math.h>

// ---------------- problem shape ----------------------------------------------
#define B_   2
#define S_   2048
#define D_   1024
#define H_   16
#define HD   64
#define MTOT (B_*S_)          // 4096
#define SCALE 0.125f          // 1/sqrt(64), exact power of two

// ---------------- baseline-PTX helpers (compile at compute_103) --------------
__device__ __forceinline__ uint32_t smem_u32(const void* p) {
    uint32_t a;
    asm("{ .reg .u64 t; cvta.to.shared.u64 t, %1; cvt.u32.u64 %0, t; }"
        : "=r"(a) : "l"(p));
    return a;
}
#define CP_ASYNC16(dst, src) \
    asm volatile("cp.async.cg.shared.global [%0], [%1], 16;" :: "r"(dst), "l"(src))
#define CP_COMMIT() asm volatile("cp.async.commit_group;" ::: "memory")
#define CP_WAIT2()  asm volatile("cp.async.wait_group 2;" ::: "memory")
#define CP_WAIT1()  asm volatile("cp.async.wait_group 1;" ::: "memory")
#define CP_WAIT0()  asm volatile("cp.async.wait_group 0;" ::: "memory")

__device__ __forceinline__ void ldsm4(uint32_t& r0, uint32_t& r1,
                                      uint32_t& r2, uint32_t& r3, uint32_t a) {
    asm volatile("ldmatrix.sync.aligned.m8n8.x4.shared.b16 {%0,%1,%2,%3}, [%4];"
                 : "=r"(r0), "=r"(r1), "=r"(r2), "=r"(r3) : "r"(a));
}
__device__ __forceinline__ void ldsm4t(uint32_t& r0, uint32_t& r1,
                                       uint32_t& r2, uint32_t& r3, uint32_t a) {
    asm volatile("ldmatrix.sync.aligned.m8n8.x4.trans.shared.b16 {%0,%1,%2,%3}, [%4];"
                 : "=r"(r0), "=r"(r1), "=r"(r2), "=r"(r3) : "r"(a));
}
__device__ __forceinline__ void mma_f16(float* c,
    uint32_t a0, uint32_t a1, uint32_t a2, uint32_t a3, uint32_t b0, uint32_t b1) {
    asm volatile("mma.sync.aligned.m16n8k16.row.col.f32.f16.f16.f32 "
                 "{%0,%1,%2,%3}, {%4,%5,%6,%7}, {%8,%9}, {%0,%1,%2,%3};"
                 : "+f"(c[0]), "+f"(c[1]), "+f"(c[2]), "+f"(c[3])
                 : "r"(a0), "r"(a1), "r"(a2), "r"(a3), "r"(b0), "r"(b1));
}
__device__ __forceinline__ uint32_t pack_h2(float a, float b) {
    __half2 t = __floats2half2_rn(a, b);     // x=a, y=b
    return *(uint32_t*)&t;
}

// ---------------- scratch (device globals; no allocations allowed) ----------
__device__ __half g_qh[(size_t)B_*H_*S_*HD], g_ql[(size_t)B_*H_*S_*HD];
__device__ __half g_kh[(size_t)B_*H_*S_*HD], g_kl[(size_t)B_*H_*S_*HD];
__device__ __half g_v [(size_t)B_*H_*S_*HD];                    // plain fp16
__device__ __half g_xh[(size_t)MTOT*D_],  g_xl[(size_t)MTOT*D_];
__device__ __half g_wh[(size_t)4*D_*D_];                         // Wq|Wk|Wv|Wo
__device__ __half g_wl[(size_t)2*D_*D_];                         // Wq|Wk lo only
__device__ __half g_ath[(size_t)MTOT*D_], g_atl[(size_t)MTOT*D_];
__device__ float2 g_rope[(size_t)S_*32];          // (cos,sin) per (spos, d/2)

// ---------------- RoPE table (exact sincosf, one-time) -----------------------
__global__ void rope_kernel(float2* __restrict__ t)
{
    int i = blockIdx.x * blockDim.x + threadIdx.x;    // over S_*32
    if (i >= S_ * 32) return;
    int spos = i >> 5, d2 = i & 31;
    float theta = powf(10000.0f, -2.0f * (float)d2 / (float)HD);
    float ang = (float)spos * theta;
    float ss, cc;
    sincosf(ang, &ss, &cc);
    t[i] = make_float2(cc, ss);
}

// ---------------- fused fp32 -> fp16 (hi[,lo]) split for x + 4 W -------------
#define RW  ((D_*D_)/4)        // 262144 float4 per weight
__global__ void split_all(const float* __restrict__ x,
                          const float* __restrict__ w0, const float* __restrict__ w1,
                          const float* __restrict__ w2, const float* __restrict__ w3,
                          __half* __restrict__ xh, __half* __restrict__ xl,
                          __half* __restrict__ wh, __half* __restrict__ wl)
{
    int i = blockIdx.x * blockDim.x + threadIdx.x;    // float4 index, 8*RW total
    const float* src;
    __half *hi, *lo;
    int local;
    if (i < 4 * RW) {
        src = x; hi = xh; lo = xl; local = i;
    } else {
        int ip = i - 4 * RW;
        int r  = ip >> 18;     // RW = 2^18
        local  = ip & (RW - 1);
        src = (r == 0) ? w0 : (r == 1) ? w1 : (r == 2) ? w2 : w3;
        hi = wh + (size_t)r * D_ * D_;
        lo = (r < 2) ? (wl + (size_t)r * D_ * D_) : nullptr;
    }
    float4 v = ((const float4*)src)[local];
    __half h0 = __float2half_rn(v.x);
    __half h1 = __float2half_rn(v.y);
    __half h2 = __float2half_rn(v.z);
    __half h3 = __float2half_rn(v.w);
    __half2 a, b;
    a.x = h0; a.y = h1; b.x = h2; b.y = h3;
    ((__half2*)hi)[2*local]   = a;
    ((__half2*)hi)[2*local+1] = b;
    if (lo) {
        a.x = __float2half_rn(v.x - __half2float(h0));
        a.y = __float2half_rn(v.y - __half2float(h1));
        b.x = __float2half_rn(v.z - __half2float(h2));
        b.y = __float2half_rn(v.w - __half2float(h3));
        ((__half2*)lo)[2*local]   = a;
        ((__half2*)lo)[2*local+1] = b;
    }
}

// ---------------- HMMA GEMM (3-stage): C[m,n] = sum_k A[m,k]*W[n,k] ----------
// A = (Ah + Al) fp16 hi/lo.  B split (3 MMAs) for Wq/Wk, plain (2 MMAs) else.
#define BKG 32
#define NKI (D_/BKG)       // 32
#define STG 32768          // bytes per stage (Ah|Al|Bh|Bl, 8K each)
#define GSMEM (3*STG)      // 96 KB

__device__ __forceinline__ uint32_t sw_off(int row, int kc) {
    return (uint32_t)((row << 6) + ((kc ^ ((row >> 1) & 3)) << 4));
}

__device__ __forceinline__ void stage_load(
    uint32_t sb, int s, int k0, int tid, int m0, int n0, int useBl,
    const __half* __restrict__ Ah, const __half* __restrict__ Al,
    const __half* __restrict__ Bh, const __half* __restrict__ Bl)
{
    const uint32_t base = sb + (uint32_t)s * STG;
#pragma unroll
    for (int p = 0; p < 2; p++) {
        const int gi  = tid + p * 256;
        const int row = gi >> 2;
        const int kc  = gi & 3;
        const uint32_t so = sw_off(row, kc);
        const size_t aoff = (size_t)(m0 + row) * D_ + k0 + kc * 8;
        const size_t boff = (size_t)(n0 + row) * D_ + k0 + kc * 8;
        CP_ASYNC16(base + 0     + so, Ah + aoff);
        CP_ASYNC16(base + 8192  + so, Al + aoff);
        CP_ASYNC16(base + 16384 + so, Bh + boff);
        if (useBl) CP_ASYNC16(base + 24576 + so, Bl + boff);
    }
}

// QKV=1: n0 in [0,3072): B = Wq|Wk|Wv rows; RoPE/scale + fp16 scatter.
// QKV=0: n0 in [0,1024): B = Wo rows; fp32 [M,D] output.
template<int QKV>
__global__ __launch_bounds__(256, 1)
void gemm_mma(const __half* __restrict__ Ah, const __half* __restrict__ Al,
              const __half* __restrict__ Bh, const __half* __restrict__ Bl,
              float* __restrict__ Cf,
              __half* __restrict__ Qh, __half* __restrict__ Ql,
              __half* __restrict__ Kh, __half* __restrict__ Kl,
              __half* __restrict__ Vp)
{
    extern __shared__ char smem[];
    const uint32_t sb = smem_u32(smem);
    const int tid  = threadIdx.x;
    const int wid  = tid >> 5;
    const int lane = tid & 31;
    const int m0 = blockIdx.y * 128;
    const int n0 = blockIdx.x * 128;
    const int wm = (wid & 1) * 64;
    const int wn = (wid >> 1) * 32;
    const int w  = QKV ? (n0 >> 10) : 3;
    const int useBl = QKV ? (w < 2) : 0;

    float acc[4][4][4];
#pragma unroll
    for (int a = 0; a < 4; a++)
#pragma unroll
        for (int b = 0; b < 4; b++)
#pragma unroll
            for (int c = 0; c < 4; c++) acc[a][b][c] = 0.f;

    stage_load(sb, 0, 0, tid, m0, n0, useBl, Ah, Al, Bh, Bl);
    CP_COMMIT();
    stage_load(sb, 1, BKG, tid, m0, n0, useBl, Ah, Al, Bh, Bl);
    CP_COMMIT();

    const int g = lane >> 3;
    const int r = lane & 7;

    for (int i = 0; i < NKI; i++) {
        if (i + 2 < NKI) {
            int s = i + 2; while (s >= 3) s -= 3;
            stage_load(sb, s, (i + 2) * BKG, tid, m0, n0, useBl, Ah, Al, Bh, Bl);
            CP_COMMIT();
            CP_WAIT2();
        } else if (i + 1 < NKI) {
            CP_WAIT1();
        } else {
            CP_WAIT0();
        }
        __syncthreads();     // cross-thread visibility of stage i's cp.asyncs
        int cs = i; while (cs >= 3) cs -= 3;
        const uint32_t base = sb + (uint32_t)cs * STG;
#pragma unroll
        for (int h = 0; h < 2; h++) {
            uint32_t ah[4][4], al[4][4], bhf[2][4], blf[2][4];
#pragma unroll
            for (int mi = 0; mi < 4; mi++) {
                const int arow = wm + mi * 16 + (g & 1) * 8 + r;
                const int akc  = h * 2 + (g >> 1);
                const uint32_t so = sw_off(arow, akc);
                ldsm4(ah[mi][0], ah[mi][1], ah[mi][2], ah[mi][3], base + 0 + so);
                ldsm4(al[mi][0], al[mi][1], al[mi][2], al[mi][3], base + 8192 + so);
            }
#pragma unroll
            for (int ng = 0; ng < 2; ng++) {
                const int brow = wn + ng * 16 + (g >> 1) * 8 + r;
                const int bkc  = h * 2 + (g & 1);
                const uint32_t so = sw_off(brow, bkc);
                ldsm4(bhf[ng][0], bhf[ng][1], bhf[ng][2], bhf[ng][3], base + 16384 + so);
                if (useBl)
                    ldsm4(blf[ng][0], blf[ng][1], blf[ng][2], blf[ng][3], base + 24576 + so);
            }
#pragma unroll
            for (int mi = 0; mi < 4; mi++)
#pragma unroll
                for (int ni = 0; ni < 4; ni++) {
                    const uint32_t* bh = &bhf[ni >> 1][(ni & 1) * 2];
                    mma_f16(acc[mi][ni], ah[mi][0], ah[mi][1], ah[mi][2], ah[mi][3], bh[0], bh[1]);
                    mma_f16(acc[mi][ni], al[mi][0], al[mi][1], al[mi][2], al[mi][3], bh[0], bh[1]);
                    if (useBl) {
                        const uint32_t* bl = &blf[ni >> 1][(ni & 1) * 2];
                        mma_f16(acc[mi][ni], ah[mi][0], ah[mi][1], ah[mi][2], ah[mi][3], bl[0], bl[1]);
                    }
                }
        }
        __syncthreads();     // all reads of this stage done before refill
    }

    // ---------------- epilogue ------------------------------------------------
    const int tg = lane >> 2;
    const int tq = lane & 3;
#pragma unroll
    for (int mi = 0; mi < 4; mi++) {
#pragma unroll
        for (int hf = 0; hf < 2; hf++) {
            const int m    = m0 + wm + mi * 16 + hf * 8 + tg;
            const int spos = m & (S_ - 1);
            const int bb   = m >> 11;
#pragma unroll
            for (int ni = 0; ni < 4; ni++) {
                const int n = n0 + wn + ni * 8 + tq * 2;     // even (global)
                float v1 = acc[mi][ni][hf * 2 + 0];
                float v2 = acc[mi][ni][hf * 2 + 1];
                if (QKV) {
                    const int nl = n & 1023;
                    const int d  = nl & (HD - 1);
                    if (w < 2) {
                        float2 cs = g_rope[spos * 32 + (d >> 1)];
                        float y1 = v1 * cs.x - v2 * cs.y;
                        float y2 = v1 * cs.y + v2 * cs.x;
                        v1 = y1; v2 = y2;
                    }
                    if (w == 0) { v1 *= SCALE; v2 *= SCALE; }
                    const int hh = nl >> 6;
                    const size_t idx = (((size_t)(bb * H_ + hh) * S_) + spos) * HD + d;
                    __half h1 = __float2half_rn(v1);
                    __half h2 = __float2half_rn(v2);
                    __half2 hp; hp.x = h1; hp.y = h2;
                    if (w == 2) {
                        *(__half2*)(Vp + idx) = hp;          // V: plain fp16
                    } else {
                        __half2 lp;
                        lp.x = __float2half_rn(v1 - __half2float(h1));
                        lp.y = __float2half_rn(v2 - __half2float(h2));
                        __half* Ch = (w == 0) ? Qh : Kh;
                        __half* Cl = (w == 0) ? Ql : Kl;
                        *(__half2*)(Ch + idx) = hp;
                        *(__half2*)(Cl + idx) = lp;
                    }
                } else {
                    float* p = Cf + (size_t)m * D_ + n;
                    *(float2*)p = make_float2(v1, v2);
                }
            }
        }
    }
}

// ---------------- HMMA flash attention (causal), fp16 -----------------------
// 128 threads (4 warps), Q tile 64 rows, K/V tiles 64 rows, double-buffered.
// QK fully compensated (q,k hi/lo, 3 MMAs); PV: P hi/lo x plain V (2 MMAs).
// Stage = KH|KL|V (8K each) = 24KB; Q staged through stage-0; smem 48KB.
#define FSTG    24576u
#define FSMEM   (2*24576)

__device__ __forceinline__ uint32_t fsw(int row, int c) {   // 128B rows
    return (uint32_t)(row * 128 + ((c ^ (row & 7)) << 4));
}

__device__ __forceinline__ void fa_stage(
    uint32_t base, const __half* kh, const __half* kl,
    const __half* v, int s0, int tid)
{
#pragma unroll
    for (int p = 0; p < 4; p++) {
        const int gi  = tid + p * 128;       // 0..511
        const int row = gi >> 3;
        const int c   = gi & 7;
        const uint32_t off = fsw(row, c);
        const size_t g = (size_t)(s0 + row) * HD + c * 8;
        CP_ASYNC16(base + 0u     + off, kh + g);
        CP_ASYNC16(base + 8192u  + off, kl + g);
        CP_ASYNC16(base + 16384u + off, v + g);
    }
}

__global__ __launch_bounds__(128, 2)
void flash_mma(const __half* __restrict__ Qh, const __half* __restrict__ Ql,
               const __half* __restrict__ Kh, const __half* __restrict__ Kl,
               const __half* __restrict__ V,
               __half* __restrict__ Oh, __half* __restrict__ Ol)
{
    extern __shared__ char smem[];
    const uint32_t sb = smem_u32(smem);
    const int tid  = threadIdx.x;
    const int wid  = tid >> 5;
    const int lane = tid & 31;
    const int bh = blockIdx.y;
    const int mt = (int)gridDim.x - 1 - (int)blockIdx.x;   // big tiles first
    const int nkt = mt + 1;                                // 64-row K tiles

    const __half* qhb = Qh + ((size_t)bh * S_) * HD;
    const __half* qlb = Ql + ((size_t)bh * S_) * HD;
    const __half* khb_ = Kh + ((size_t)bh * S_) * HD;
    const __half* klb_ = Kl + ((size_t)bh * S_) * HD;
    const __half* vb_  = V  + ((size_t)bh * S_) * HD;

    const int grp = lane >> 3;
    const int rr  = lane & 7;

    // ---- stage Q through stage-0 buffer, extract frags to registers --------
#pragma unroll
    for (int p = 0; p < 4; p++) {
        const int gi  = tid + p * 128;       // 0..511
        const int row = gi >> 3;
        const int c   = gi & 7;
        const uint32_t off = fsw(row, c);
        const size_t g = (size_t)(mt * 64 + row) * HD + c * 8;
        CP_ASYNC16(sb + 0u    + off, qhb + g);
        CP_ASYNC16(sb + 8192u + off, qlb + g);
    }
    CP_COMMIT();
    CP_WAIT0();
    __syncthreads();

    uint32_t qhf[4][4], qlf[4][4];
#pragma unroll
    for (int kc = 0; kc < 4; kc++) {
        const int row = wid * 16 + (grp & 1) * 8 + rr;
        const int c   = kc * 2 + (grp >> 1);
        const uint32_t off = fsw(row, c);
        ldsm4(qhf[kc][0], qhf[kc][1], qhf[kc][2], qhf[kc][3], sb + 0u + off);
        ldsm4(qlf[kc][0], qlf[kc][1], qlf[kc][2], qlf[kc][3], sb + 8192u + off);
    }
    __syncthreads();     // Q frags extracted before stage-0 is overwritten

    fa_stage(sb, khb_, klb_, vb_, 0, tid);
    CP_COMMIT();

    float o[8][4];
#pragma unroll
    for (int a = 0; a < 8; a++)
#pragma unroll
        for (int b = 0; b < 4; b++) o[a][b] = 0.f;
    float m0r = -1e30f, m1r = -1e30f, l0r = 0.f, l1r = 0.f;

    for (int kt = 0; kt < nkt; kt++) {
        if (kt + 1 < nkt) {
            fa_stage(sb + (uint32_t)((kt + 1) & 1) * FSTG,
                     khb_, klb_, vb_, (kt + 1) * 64, tid);
            CP_COMMIT();
            CP_WAIT1();
        } else {
            CP_WAIT0();
        }
        __syncthreads();     // stage kt visible to all threads

        const uint32_t st = sb + (uint32_t)(kt & 1) * FSTG;

        // ---- scores S = Q K^T (3-MMA compensated) ------------------------
        float c[8][4];
#pragma unroll
        for (int a = 0; a < 8; a++)
#pragma unroll
            for (int b = 0; b < 4; b++) c[a][b] = 0.f;

#pragma unroll
        for (int nt = 0; nt < 8; nt++) {
            const int j = nt * 8 + rr;
            uint32_t kb0[4], kb1[4], lb0[4], lb1[4];
            ldsm4(kb0[0], kb0[1], kb0[2], kb0[3], st + 0u    + fsw(j, 0 + grp));
            ldsm4(kb1[0], kb1[1], kb1[2], kb1[3], st + 0u    + fsw(j, 4 + grp));
            ldsm4(lb0[0], lb0[1], lb0[2], lb0[3], st + 8192u + fsw(j, 0 + grp));
            ldsm4(lb1[0], lb1[1], lb1[2], lb1[3], st + 8192u + fsw(j, 4 + grp));
            mma_f16(c[nt], qhf[0][0], qhf[0][1], qhf[0][2], qhf[0][3], kb0[0], kb0[1]);
            mma_f16(c[nt], qhf[0][0], qhf[0][1], qhf[0][2], qhf[0][3], lb0[0], lb0[1]);
            mma_f16(c[nt], qlf[0][0], qlf[0][1], qlf[0][2], qlf[0][3], kb0[0], kb0[1]);
            mma_f16(c[nt], qhf[1][0], qhf[1][1], qhf[1][2], qhf[1][3], kb0[2], kb0[3]);
            mma_f16(c[nt], qhf[1][0], qhf[1][1], qhf[1][2], qhf[1][3], lb0[2], lb0[3]);
            mma_f16(c[nt], qlf[1][0], qlf[1][1], qlf[1][2], qlf[1][3], kb0[2], kb0[3]);
            mma_f16(c[nt], qhf[2][0], qhf[2][1], qhf[2][2], qhf[2][3], kb1[0], kb1[1]);
            mma_f16(c[nt], qhf[2][0], qhf[2][1], qhf[2][2], qhf[2][3], lb1[0], lb1[1]);
            mma_f16(c[nt], qlf[2][0], qlf[2][1], qlf[2][2], qlf[2][3], kb1[0], kb1[1]);
            mma_f16(c[nt], qhf[3][0], qhf[3][1], qhf[3][2], qhf[3][3], kb1[2], kb1[3]);
            mma_f16(c[nt], qhf[3][0], qhf[3][1], qhf[3][2], qhf[3][3], lb1[2], lb1[3]);
            mma_f16(c[nt], qlf[3][0], qlf[3][1], qlf[3][2], qlf[3][3], kb1[2], kb1[3]);
        }

        // ---- causal mask on diagonal tile --------------------------------
        if (kt == mt) {
            const int i0 = wid * 16 + (lane >> 2);
#pragma unroll
            for (int nt = 0; nt < 8; nt++) {
                const int j0 = nt * 8 + (lane & 3) * 2;
                if (j0     > i0)     c[nt][0] = -1e30f;
                if (j0 + 1 > i0)     c[nt][1] = -1e30f;
                if (j0     > i0 + 8) c[nt][2] = -1e30f;
                if (j0 + 1 > i0 + 8) c[nt][3] = -1e30f;
            }
        }

        // ---- online softmax ----------------------------------------------
        float t0 = -1e30f, t1 = -1e30f;
#pragma unroll
        for (int nt = 0; nt < 8; nt++) {
            t0 = fmaxf(t0, fmaxf(c[nt][0], c[nt][1]));
            t1 = fmaxf(t1, fmaxf(c[nt][2], c[nt][3]));
        }
        t0 = fmaxf(t0, __shfl_xor_sync(0xffffffffu, t0, 1));
        t0 = fmaxf(t0, __shfl_xor_sync(0xffffffffu, t0, 2));
        t1 = fmaxf(t1, __shfl_xor_sync(0xffffffffu, t1, 1));
        t1 = fmaxf(t1, __shfl_xor_sync(0xffffffffu, t1, 2));
        const float mn0 = fmaxf(m0r, t0);
        const float mn1 = fmaxf(m1r, t1);
        const float al0 = __expf(m0r - mn0);
        const float al1 = __expf(m1r - mn1);
        m0r = mn0; m1r = mn1;

        float s0 = 0.f, s1 = 0.f;
#pragma unroll
        for (int nt = 0; nt < 8; nt++) {
            c[nt][0] = __expf(c[nt][0] - mn0);
            c[nt][1] = __expf(c[nt][1] - mn0);
            c[nt][2] = __expf(c[nt][2] - mn1);
            c[nt][3] = __expf(c[nt][3] - mn1);
            s0 += c[nt][0] + c[nt][1];
            s1 += c[nt][2] + c[nt][3];
        }
        s0 += __shfl_xor_sync(0xffffffffu, s0, 1);
        s0 += __shfl_xor_sync(0xffffffffu, s0, 2);
        s1 += __shfl_xor_sync(0xffffffffu, s1, 1);
        s1 += __shfl_xor_sync(0xffffffffu, s1, 2);
        l0r = l0r * al0 + s0;
        l1r = l1r * al1 + s1;

#pragma unroll
        for (int nt = 0; nt < 8; nt++) {
            o[nt][0] *= al0; o[nt][1] *= al0;
            o[nt][2] *= al1; o[nt][3] *= al1;
        }

        // ---- O += P V (P hi/lo fp16, V plain -> 2 MMAs per frag) ---------
#pragma unroll
        for (int kc = 0; kc < 4; kc++) {
            uint32_t ph[4], pl[4];
            const float* p0 = c[2*kc];
            const float* p1 = c[2*kc+1];
            ph[0] = pack_h2(p0[0], p0[1]);
            ph[1] = pack_h2(p0[2], p0[3]);
            ph[2] = pack_h2(p1[0], p1[1]);
            ph[3] = pack_h2(p1[2], p1[3]);
            __half2 hh;
            *(uint32_t*)&hh = ph[0];
            pl[0] = pack_h2(p0[0]-__half2float(hh.x), p0[1]-__half2float(hh.y));
            *(uint32_t*)&hh = ph[1];
            pl[1] = pack_h2(p0[2]-__half2float(hh.x), p0[3]-__half2float(hh.y));
            *(uint32_t*)&hh = ph[2];
            pl[2] = pack_h2(p1[0]-__half2float(hh.x), p1[1]-__half2float(hh.y));
            *(uint32_t*)&hh = ph[3];
            pl[3] = pack_h2(p1[2]-__half2float(hh.x), p1[3]-__half2float(hh.y));
#pragma unroll
            for (int ntp = 0; ntp < 4; ntp++) {
                const int row = kc * 16 + (grp & 1) * 8 + rr;
                const int ch  = ntp * 2 + (grp >> 1);
                const uint32_t off = fsw(row, ch);
                uint32_t v0, v1, v2, v3;
                ldsm4t(v0, v1, v2, v3, st + 16384u + off);
                mma_f16(o[2*ntp],   ph[0], ph[1], ph[2], ph[3], v0, v1);
                mma_f16(o[2*ntp],   pl[0], pl[1], pl[2], pl[3], v0, v1);
                mma_f16(o[2*ntp+1], ph[0], ph[1], ph[2], ph[3], v2, v3);
                mma_f16(o[2*ntp+1], pl[0], pl[1], pl[2], pl[3], v2, v3);
            }
        }
        __syncthreads();     // all reads of this buffer done before refill
    }

    // ---- finalize + write fp16 hi/lo [B,S,D] --------------------------------
    const float inv0 = 1.f / l0r;
    const float inv1 = 1.f / l1r;
    const int b = bh >> 4;
    const int h = bh & (H_ - 1);
    const int sq0 = mt * 64 + wid * 16 + (lane >> 2);
    const size_t base0 = ((size_t)(b * S_ + sq0)) * D_ + h * HD;
    const size_t base1 = base0 + (size_t)8 * D_;
#pragma unroll
    for (int nt = 0; nt < 8; nt++) {
        const int col = nt * 8 + (lane & 3) * 2;
        {
            float v0 = o[nt][0] * inv0, v1 = o[nt][1] * inv0;
            __half h0 = __float2half_rn(v0);
            __half h1 = __float2half_rn(v1);
            __half2 hp; hp.x = h0; hp.y = h1;
            __half2 lp;
            lp.x = __float2half_rn(v0 - __half2float(h0));
            lp.y = __float2half_rn(v1 - __half2float(h1));
            *(__half2*)(Oh + base0 + col) = hp;
            *(__half2*)(Ol + base0 + col) = lp;
        }
        {
            float v0 = o[nt][2] * inv1, v1 = o[nt][3] * inv1;
            __half h0 = __float2half_rn(v0);
            __half h1 = __float2half_rn(v1);
            __half2 hp; hp.x = h0; hp.y = h1;
            __half2 lp;
            lp.x = __float2half_rn(v0 - __half2float(h0));
            lp.y = __float2half_rn(v1 - __half2float(h1));
            *(__half2*)(Oh + base1 + col) = hp;
            *(__half2*)(Ol + base1 + col) = lp;
        }
    }
}

// ---------------- launch -----------------------------------------------------
extern "C" void kernel_launch(void* const* d_in, const int* in_sizes, int n_in,
                              void* d_out, int out_size)
{
    const float* x  = (const float*)d_in[0];
    float* out = (float*)d_out;

    void *pqh, *pql, *pkh, *pkl, *pv, *pxh, *pxl, *pwh, *pwl, *path, *patl, *prope;
    cudaGetSymbolAddress(&pqh, g_qh);  cudaGetSymbolAddress(&pql, g_ql);
    cudaGetSymbolAddress(&pkh, g_kh);  cudaGetSymbolAddress(&pkl, g_kl);
    cudaGetSymbolAddress(&pv,  g_v);
    cudaGetSymbolAddress(&pxh, g_xh);  cudaGetSymbolAddress(&pxl, g_xl);
    cudaGetSymbolAddress(&pwh, g_wh);  cudaGetSymbolAddress(&pwl, g_wl);
    cudaGetSymbolAddress(&path, g_ath); cudaGetSymbolAddress(&patl, g_atl);
    cudaGetSymbolAddress(&prope, g_rope);

    cudaFuncSetAttribute(gemm_mma<1>, cudaFuncAttributeMaxDynamicSharedMemorySize, GSMEM);
    cudaFuncSetAttribute(gemm_mma<0>, cudaFuncAttributeMaxDynamicSharedMemorySize, GSMEM);
    cudaFuncSetAttribute(flash_mma, cudaFuncAttributeMaxDynamicSharedMemorySize, FSMEM);

    __half* xh = (__half*)pxh;
    __half* xl = (__half*)pxl;
    __half* wh = (__half*)pwh;
    __half* wl = (__half*)pwl;

    // RoPE table + fused splits
    rope_kernel<<<(S_ * 32 + 255) / 256, 256>>>((float2*)prope);
    split_all<<<(8 * RW) / 256, 256>>>(x, (const float*)d_in[1], (const float*)d_in[2],
                                       (const float*)d_in[3], (const float*)d_in[4],
                                       xh, xl, wh, wl);

    // fused QKV projection -> fp16 [B,H,S,hd] (Q,K hi/lo; V plain)
    dim3 qkvgrid(3 * D_ / 128, MTOT / 128);   // (24, 32)
    gemm_mma<1><<<qkvgrid, 256, GSMEM>>>(xh, xl, wh, wl, nullptr,
        (__half*)pqh, (__half*)pql, (__half*)pkh, (__half*)pkl, (__half*)pv);

    // tensor-core causal flash attention -> fp16 hi/lo [B,S,D]
    dim3 agrid(S_ / 64, B_ * H_);        // (32, 32)
    flash_mma<<<agrid, 128, FSMEM>>>((const __half*)pqh, (const __half*)pql,
                                     (const __half*)pkh, (const __half*)pkl,
                                     (const __half*)pv,
                                     (__half*)path, (__half*)patl);

    // output projection -> d_out (fp32), Wo plain (2-MMA)
    dim3 ogrid(D_ / 128, MTOT / 128);    // (8, 32)
    gemm_mma<0><<<ogrid, 256, GSMEM>>>((const __half*)path, (const __half*)patl,
                                       wh + 3*(size_t)D_*D_, wl,
                                       out, nullptr, nullptr, nullptr, nullptr, nullptr);
}

// round 10
// speedup vs baseline: 1.2591x; 1.0987x over previous
#include <cuda_runtime.h>
#include <cuda_fp16.h>
#include <cstdint>
#include <math.h>

// ---------------- problem shape ----------------------------------------------
#define B_   2
#define S_   2048
#define D_   1024
#define H_   16
#define HD   64
#define MTOT (B_*S_)          // 4096
#define SCALE 0.125f          // 1/sqrt(64), exact power of two

// ---------------- baseline-PTX helpers (compile at compute_103) --------------
__device__ __forceinline__ uint32_t smem_u32(const void* p) {
    uint32_t a;
    asm("{ .reg .u64 t; cvta.to.shared.u64 t, %1; cvt.u32.u64 %0, t; }"
        : "=r"(a) : "l"(p));
    return a;
}
#define CP_ASYNC16(dst, src) \
    asm volatile("cp.async.cg.shared.global [%0], [%1], 16;" :: "r"(dst), "l"(src))
#define CP_COMMIT() asm volatile("cp.async.commit_group;" ::: "memory")
#define CP_WAIT2()  asm volatile("cp.async.wait_group 2;" ::: "memory")
#define CP_WAIT1()  asm volatile("cp.async.wait_group 1;" ::: "memory")
#define CP_WAIT0()  asm volatile("cp.async.wait_group 0;" ::: "memory")

__device__ __forceinline__ void ldsm4(uint32_t& r0, uint32_t& r1,
                                      uint32_t& r2, uint32_t& r3, uint32_t a) {
    asm volatile("ldmatrix.sync.aligned.m8n8.x4.shared.b16 {%0,%1,%2,%3}, [%4];"
                 : "=r"(r0), "=r"(r1), "=r"(r2), "=r"(r3) : "r"(a));
}
__device__ __forceinline__ void ldsm4t(uint32_t& r0, uint32_t& r1,
                                       uint32_t& r2, uint32_t& r3, uint32_t a) {
    asm volatile("ldmatrix.sync.aligned.m8n8.x4.trans.shared.b16 {%0,%1,%2,%3}, [%4];"
                 : "=r"(r0), "=r"(r1), "=r"(r2), "=r"(r3) : "r"(a));
}
__device__ __forceinline__ void mma_f16(float* c,
    uint32_t a0, uint32_t a1, uint32_t a2, uint32_t a3, uint32_t b0, uint32_t b1) {
    asm volatile("mma.sync.aligned.m16n8k16.row.col.f32.f16.f16.f32 "
                 "{%0,%1,%2,%3}, {%4,%5,%6,%7}, {%8,%9}, {%0,%1,%2,%3};"
                 : "+f"(c[0]), "+f"(c[1]), "+f"(c[2]), "+f"(c[3])
                 : "r"(a0), "r"(a1), "r"(a2), "r"(a3), "r"(b0), "r"(b1));
}
__device__ __forceinline__ uint32_t pack_h2(float a, float b) {
    __half2 t = __floats2half2_rn(a, b);     // x=a, y=b
    return *(uint32_t*)&t;
}

// ---------------- scratch (device globals; no allocations allowed) ----------
__device__ __half g_qh[(size_t)B_*H_*S_*HD], g_ql[(size_t)B_*H_*S_*HD];
__device__ __half g_kh[(size_t)B_*H_*S_*HD], g_kl[(size_t)B_*H_*S_*HD];
__device__ __half g_v [(size_t)B_*H_*S_*HD];                    // plain fp16
__device__ __half g_xh[(size_t)MTOT*D_],  g_xl[(size_t)MTOT*D_];
__device__ __half g_wh[(size_t)4*D_*D_];                         // Wq|Wk|Wv|Wo
__device__ __half g_wl[(size_t)2*D_*D_];                         // Wq|Wk lo only
__device__ __half g_att[(size_t)MTOT*D_];                        // attention out, plain
__device__ float2 g_rope[(size_t)S_*32];          // (cos,sin) per (spos, d/2)

// ---------------- RoPE table (exact sincosf, one-time) -----------------------
__global__ void rope_kernel(float2* __restrict__ t)
{
    int i = blockIdx.x * blockDim.x + threadIdx.x;    // over S_*32
    if (i >= S_ * 32) return;
    int spos = i >> 5, d2 = i & 31;
    float theta = powf(10000.0f, -2.0f * (float)d2 / (float)HD);
    float ang = (float)spos * theta;
    float ss, cc;
    sincosf(ang, &ss, &cc);
    t[i] = make_float2(cc, ss);
}

// ---------------- fused fp32 -> fp16 (hi[,lo]) split for x + 4 W -------------
#define RW  ((D_*D_)/4)        // 262144 float4 per weight
__global__ void split_all(const float* __restrict__ x,
                          const float* __restrict__ w0, const float* __restrict__ w1,
                          const float* __restrict__ w2, const float* __restrict__ w3,
                          __half* __restrict__ xh, __half* __restrict__ xl,
                          __half* __restrict__ wh, __half* __restrict__ wl)
{
    int i = blockIdx.x * blockDim.x + threadIdx.x;    // float4 index, 8*RW total
    const float* src;
    __half *hi, *lo;
    int local;
    if (i < 4 * RW) {
        src = x; hi = xh; lo = xl; local = i;
    } else {
        int ip = i - 4 * RW;
        int r  = ip >> 18;     // RW = 2^18
        local  = ip & (RW - 1);
        src = (r == 0) ? w0 : (r == 1) ? w1 : (r == 2) ? w2 : w3;
        hi = wh + (size_t)r * D_ * D_;
        lo = (r < 2) ? (wl + (size_t)r * D_ * D_) : nullptr;
    }
    float4 v = ((const float4*)src)[local];
    __half h0 = __float2half_rn(v.x);
    __half h1 = __float2half_rn(v.y);
    __half h2 = __float2half_rn(v.z);
    __half h3 = __float2half_rn(v.w);
    __half2 a, b;
    a.x = h0; a.y = h1; b.x = h2; b.y = h3;
    ((__half2*)hi)[2*local]   = a;
    ((__half2*)hi)[2*local+1] = b;
    if (lo) {
        a.x = __float2half_rn(v.x - __half2float(h0));
        a.y = __float2half_rn(v.y - __half2float(h1));
        b.x = __float2half_rn(v.z - __half2float(h2));
        b.y = __float2half_rn(v.w - __half2float(h3));
        ((__half2*)lo)[2*local]   = a;
        ((__half2*)lo)[2*local+1] = b;
    }
}

// ---------------- HMMA GEMM (3-stage): C[m,n] = sum_k A[m,k]*W[n,k] ----------
// MMA count per fragment: 1 + useAl + useBl (compensation terms).
#define BKG 32
#define NKI (D_/BKG)       // 32
#define STG 32768          // bytes per stage (Ah|Al|Bh|Bl, 8K each)
#define GSMEM (3*STG)      // 96 KB

__device__ __forceinline__ uint32_t sw_off(int row, int kc) {
    return (uint32_t)((row << 6) + ((kc ^ ((row >> 1) & 3)) << 4));
}

__device__ __forceinline__ void stage_load(
    uint32_t sb, int s, int k0, int tid, int m0, int n0, int useAl, int useBl,
    const __half* __restrict__ Ah, const __half* __restrict__ Al,
    const __half* __restrict__ Bh, const __half* __restrict__ Bl)
{
    const uint32_t base = sb + (uint32_t)s * STG;
#pragma unroll
    for (int p = 0; p < 2; p++) {
        const int gi  = tid + p * 256;
        const int row = gi >> 2;
        const int kc  = gi & 3;
        const uint32_t so = sw_off(row, kc);
        const size_t aoff = (size_t)(m0 + row) * D_ + k0 + kc * 8;
        const size_t boff = (size_t)(n0 + row) * D_ + k0 + kc * 8;
        CP_ASYNC16(base + 0     + so, Ah + aoff);
        if (useAl) CP_ASYNC16(base + 8192  + so, Al + aoff);
        CP_ASYNC16(base + 16384 + so, Bh + boff);
        if (useBl) CP_ASYNC16(base + 24576 + so, Bl + boff);
    }
}

// QKV=1: n0 in [0,3072): B = Wq|Wk|Wv rows; RoPE/scale + fp16 scatter.
//        Q,K: x split + W split (3 MMAs); V: plain x plain (1 MMA).
// QKV=0: n0 in [0,1024): B = Wo rows, A = att plain (1 MMA); fp32 output.
template<int QKV>
__global__ __launch_bounds__(256, 1)
void gemm_mma(const __half* __restrict__ Ah, const __half* __restrict__ Al,
              const __half* __restrict__ Bh, const __half* __restrict__ Bl,
              float* __restrict__ Cf,
              __half* __restrict__ Qh, __half* __restrict__ Ql,
              __half* __restrict__ Kh, __half* __restrict__ Kl,
              __half* __restrict__ Vp)
{
    extern __shared__ char smem[];
    const uint32_t sb = smem_u32(smem);
    const int tid  = threadIdx.x;
    const int wid  = tid >> 5;
    const int lane = tid & 31;
    const int m0 = blockIdx.y * 128;
    const int n0 = blockIdx.x * 128;
    const int wm = (wid & 1) * 64;
    const int wn = (wid >> 1) * 32;
    const int w  = QKV ? (n0 >> 10) : 3;
    const int useAl = QKV ? (w < 2) : 0;     // x compensation only for Q,K
    const int useBl = QKV ? (w < 2) : 0;     // W compensation only for Wq,Wk

    float acc[4][4][4];
#pragma unroll
    for (int a = 0; a < 4; a++)
#pragma unroll
        for (int b = 0; b < 4; b++)
#pragma unroll
            for (int c = 0; c < 4; c++) acc[a][b][c] = 0.f;

    stage_load(sb, 0, 0, tid, m0, n0, useAl, useBl, Ah, Al, Bh, Bl);
    CP_COMMIT();
    stage_load(sb, 1, BKG, tid, m0, n0, useAl, useBl, Ah, Al, Bh, Bl);
    CP_COMMIT();

    const int g = lane >> 3;
    const int r = lane & 7;

    for (int i = 0; i < NKI; i++) {
        if (i + 2 < NKI) {
            int s = i + 2; while (s >= 3) s -= 3;
            stage_load(sb, s, (i + 2) * BKG, tid, m0, n0, useAl, useBl, Ah, Al, Bh, Bl);
            CP_COMMIT();
            CP_WAIT2();
        } else if (i + 1 < NKI) {
            CP_WAIT1();
        } else {
            CP_WAIT0();
        }
        __syncthreads();     // cross-thread visibility of stage i's cp.asyncs
        int cs = i; while (cs >= 3) cs -= 3;
        const uint32_t base = sb + (uint32_t)cs * STG;
#pragma unroll
        for (int h = 0; h < 2; h++) {
            uint32_t ah[4][4], al[4][4], bhf[2][4], blf[2][4];
#pragma unroll
            for (int mi = 0; mi < 4; mi++) {
                const int arow = wm + mi * 16 + (g & 1) * 8 + r;
                const int akc  = h * 2 + (g >> 1);
                const uint32_t so = sw_off(arow, akc);
                ldsm4(ah[mi][0], ah[mi][1], ah[mi][2], ah[mi][3], base + 0 + so);
                if (useAl)
                    ldsm4(al[mi][0], al[mi][1], al[mi][2], al[mi][3], base + 8192 + so);
            }
#pragma unroll
            for (int ng = 0; ng < 2; ng++) {
                const int brow = wn + ng * 16 + (g >> 1) * 8 + r;
                const int bkc  = h * 2 + (g & 1);
                const uint32_t so = sw_off(brow, bkc);
                ldsm4(bhf[ng][0], bhf[ng][1], bhf[ng][2], bhf[ng][3], base + 16384 + so);
                if (useBl)
                    ldsm4(blf[ng][0], blf[ng][1], blf[ng][2], blf[ng][3], base + 24576 + so);
            }
#pragma unroll
            for (int mi = 0; mi < 4; mi++)
#pragma unroll
                for (int ni = 0; ni < 4; ni++) {
                    const uint32_t* bh = &bhf[ni >> 1][(ni & 1) * 2];
                    mma_f16(acc[mi][ni], ah[mi][0], ah[mi][1], ah[mi][2], ah[mi][3], bh[0], bh[1]);
                    if (useAl)
                        mma_f16(acc[mi][ni], al[mi][0], al[mi][1], al[mi][2], al[mi][3], bh[0], bh[1]);
                    if (useBl) {
                        const uint32_t* bl = &blf[ni >> 1][(ni & 1) * 2];
                        mma_f16(acc[mi][ni], ah[mi][0], ah[mi][1], ah[mi][2], ah[mi][3], bl[0], bl[1]);
                    }
                }
        }
        __syncthreads();     // all reads of this stage done before refill
    }

    // ---------------- epilogue ------------------------------------------------
    const int tg = lane >> 2;
    const int tq = lane & 3;
#pragma unroll
    for (int mi = 0; mi < 4; mi++) {
#pragma unroll
        for (int hf = 0; hf < 2; hf++) {
            const int m    = m0 + wm + mi * 16 + hf * 8 + tg;
            const int spos = m & (S_ - 1);
            const int bb   = m >> 11;
#pragma unroll
            for (int ni = 0; ni < 4; ni++) {
                const int n = n0 + wn + ni * 8 + tq * 2;     // even (global)
                float v1 = acc[mi][ni][hf * 2 + 0];
                float v2 = acc[mi][ni][hf * 2 + 1];
                if (QKV) {
                    const int nl = n & 1023;
                    const int d  = nl & (HD - 1);
                    if (w < 2) {
                        float2 cs = g_rope[spos * 32 + (d >> 1)];
                        float y1 = v1 * cs.x - v2 * cs.y;
                        float y2 = v1 * cs.y + v2 * cs.x;
                        v1 = y1; v2 = y2;
                    }
                    if (w == 0) { v1 *= SCALE; v2 *= SCALE; }
                    const int hh = nl >> 6;
                    const size_t idx = (((size_t)(bb * H_ + hh) * S_) + spos) * HD + d;
                    __half h1 = __float2half_rn(v1);
                    __half h2 = __float2half_rn(v2);
                    __half2 hp; hp.x = h1; hp.y = h2;
                    if (w == 2) {
                        *(__half2*)(Vp + idx) = hp;          // V: plain fp16
                    } else {
                        __half2 lp;
                        lp.x = __float2half_rn(v1 - __half2float(h1));
                        lp.y = __float2half_rn(v2 - __half2float(h2));
                        __half* Ch = (w == 0) ? Qh : Kh;
                        __half* Cl = (w == 0) ? Ql : Kl;
                        *(__half2*)(Ch + idx) = hp;
                        *(__half2*)(Cl + idx) = lp;
                    }
                } else {
                    float* p = Cf + (size_t)m * D_ + n;
                    *(float2*)p = make_float2(v1, v2);
                }
            }
        }
    }
}

// ---------------- HMMA flash attention (causal), fp16 -----------------------
// 128 threads (4 warps), Q tile 64 rows, K/V tiles 64 rows, double-buffered.
// QK compensated (q,k hi/lo, 3 MMAs); PV: P plain x V plain (1 MMA).
// Stage = KH|KL|V (8K each) = 24KB; Q staged through stage-0; smem 48KB.
#define FSTG    24576u
#define FSMEM   (2*24576)

__device__ __forceinline__ uint32_t fsw(int row, int c) {   // 128B rows
    return (uint32_t)(row * 128 + ((c ^ (row & 7)) << 4));
}

__device__ __forceinline__ void fa_stage(
    uint32_t base, const __half* kh, const __half* kl,
    const __half* v, int s0, int tid)
{
#pragma unroll
    for (int p = 0; p < 4; p++) {
        const int gi  = tid + p * 128;       // 0..511
        const int row = gi >> 3;
        const int c   = gi & 7;
        const uint32_t off = fsw(row, c);
        const size_t g = (size_t)(s0 + row) * HD + c * 8;
        CP_ASYNC16(base + 0u     + off, kh + g);
        CP_ASYNC16(base + 8192u  + off, kl + g);
        CP_ASYNC16(base + 16384u + off, v + g);
    }
}

__global__ __launch_bounds__(128, 2)
void flash_mma(const __half* __restrict__ Qh, const __half* __restrict__ Ql,
               const __half* __restrict__ Kh, const __half* __restrict__ Kl,
               const __half* __restrict__ V,
               __half* __restrict__ Oatt)
{
    extern __shared__ char smem[];
    const uint32_t sb = smem_u32(smem);
    const int tid  = threadIdx.x;
    const int wid  = tid >> 5;
    const int lane = tid & 31;
    const int bh = blockIdx.y;
    const int mt = (int)gridDim.x - 1 - (int)blockIdx.x;   // big tiles first
    const int nkt = mt + 1;                                // 64-row K tiles

    const __half* qhb = Qh + ((size_t)bh * S_) * HD;
    const __half* qlb = Ql + ((size_t)bh * S_) * HD;
    const __half* khb_ = Kh + ((size_t)bh * S_) * HD;
    const __half* klb_ = Kl + ((size_t)bh * S_) * HD;
    const __half* vb_  = V  + ((size_t)bh * S_) * HD;

    const int grp = lane >> 3;
    const int rr  = lane & 7;

    // ---- stage Q through stage-0 buffer, extract frags to registers --------
#pragma unroll
    for (int p = 0; p < 4; p++) {
        const int gi  = tid + p * 128;       // 0..511
        const int row = gi >> 3;
        const int c   = gi & 7;
        const uint32_t off = fsw(row, c);
        const size_t g = (size_t)(mt * 64 + row) * HD + c * 8;
        CP_ASYNC16(sb + 0u    + off, qhb + g);
        CP_ASYNC16(sb + 8192u + off, qlb + g);
    }
    CP_COMMIT();
    CP_WAIT0();
    __syncthreads();

    uint32_t qhf[4][4], qlf[4][4];
#pragma unroll
    for (int kc = 0; kc < 4; kc++) {
        const int row = wid * 16 + (grp & 1) * 8 + rr;
        const int c   = kc * 2 + (grp >> 1);
        const uint32_t off = fsw(row, c);
        ldsm4(qhf[kc][0], qhf[kc][1], qhf[kc][2], qhf[kc][3], sb + 0u + off);
        ldsm4(qlf[kc][0], qlf[kc][1], qlf[kc][2], qlf[kc][3], sb + 8192u + off);
    }
    __syncthreads();     // Q frags extracted before stage-0 is overwritten

    fa_stage(sb, khb_, klb_, vb_, 0, tid);
    CP_COMMIT();

    float o[8][4];
#pragma unroll
    for (int a = 0; a < 8; a++)
#pragma unroll
        for (int b = 0; b < 4; b++) o[a][b] = 0.f;
    float m0r = -1e30f, m1r = -1e30f, l0r = 0.f, l1r = 0.f;

    for (int kt = 0; kt < nkt; kt++) {
        if (kt + 1 < nkt) {
            fa_stage(sb + (uint32_t)((kt + 1) & 1) * FSTG,
                     khb_, klb_, vb_, (kt + 1) * 64, tid);
            CP_COMMIT();
            CP_WAIT1();
        } else {
            CP_WAIT0();
        }
        __syncthreads();     // stage kt visible to all threads

        const uint32_t st = sb + (uint32_t)(kt & 1) * FSTG;

        // ---- scores S = Q K^T (3-MMA compensated) ------------------------
        float c[8][4];
#pragma unroll
        for (int a = 0; a < 8; a++)
#pragma unroll
            for (int b = 0; b < 4; b++) c[a][b] = 0.f;

#pragma unroll
        for (int nt = 0; nt < 8; nt++) {
            const int j = nt * 8 + rr;
            uint32_t kb0[4], kb1[4], lb0[4], lb1[4];
            ldsm4(kb0[0], kb0[1], kb0[2], kb0[3], st + 0u    + fsw(j, 0 + grp));
            ldsm4(kb1[0], kb1[1], kb1[2], kb1[3], st + 0u    + fsw(j, 4 + grp));
            ldsm4(lb0[0], lb0[1], lb0[2], lb0[3], st + 8192u + fsw(j, 0 + grp));
            ldsm4(lb1[0], lb1[1], lb1[2], lb1[3], st + 8192u + fsw(j, 4 + grp));
            mma_f16(c[nt], qhf[0][0], qhf[0][1], qhf[0][2], qhf[0][3], kb0[0], kb0[1]);
            mma_f16(c[nt], qhf[0][0], qhf[0][1], qhf[0][2], qhf[0][3], lb0[0], lb0[1]);
            mma_f16(c[nt], qlf[0][0], qlf[0][1], qlf[0][2], qlf[0][3], kb0[0], kb0[1]);
            mma_f16(c[nt], qhf[1][0], qhf[1][1], qhf[1][2], qhf[1][3], kb0[2], kb0[3]);
            mma_f16(c[nt], qhf[1][0], qhf[1][1], qhf[1][2], qhf[1][3], lb0[2], lb0[3]);
            mma_f16(c[nt], qlf[1][0], qlf[1][1], qlf[1][2], qlf[1][3], kb0[2], kb0[3]);
            mma_f16(c[nt], qhf[2][0], qhf[2][1], qhf[2][2], qhf[2][3], kb1[0], kb1[1]);
            mma_f16(c[nt], qhf[2][0], qhf[2][1], qhf[2][2], qhf[2][3], lb1[0], lb1[1]);
            mma_f16(c[nt], qlf[2][0], qlf[2][1], qlf[2][2], qlf[2][3], kb1[0], kb1[1]);
            mma_f16(c[nt], qhf[3][0], qhf[3][1], qhf[3][2], qhf[3][3], kb1[2], kb1[3]);
            mma_f16(c[nt], qhf[3][0], qhf[3][1], qhf[3][2], qhf[3][3], lb1[2], lb1[3]);
            mma_f16(c[nt], qlf[3][0], qlf[3][1], qlf[3][2], qlf[3][3], kb1[2], kb1[3]);
        }

        // ---- causal mask on diagonal tile --------------------------------
        if (kt == mt) {
            const int i0 = wid * 16 + (lane >> 2);
#pragma unroll
            for (int nt = 0; nt < 8; nt++) {
                const int j0 = nt * 8 + (lane & 3) * 2;
                if (j0     > i0)     c[nt][0] = -1e30f;
                if (j0 + 1 > i0)     c[nt][1] = -1e30f;
                if (j0     > i0 + 8) c[nt][2] = -1e30f;
                if (j0 + 1 > i0 + 8) c[nt][3] = -1e30f;
            }
        }

        // ---- online softmax ----------------------------------------------
        float t0 = -1e30f, t1 = -1e30f;
#pragma unroll
        for (int nt = 0; nt < 8; nt++) {
            t0 = fmaxf(t0, fmaxf(c[nt][0], c[nt][1]));
            t1 = fmaxf(t1, fmaxf(c[nt][2], c[nt][3]));
        }
        t0 = fmaxf(t0, __shfl_xor_sync(0xffffffffu, t0, 1));
        t0 = fmaxf(t0, __shfl_xor_sync(0xffffffffu, t0, 2));
        t1 = fmaxf(t1, __shfl_xor_sync(0xffffffffu, t1, 1));
        t1 = fmaxf(t1, __shfl_xor_sync(0xffffffffu, t1, 2));
        const float mn0 = fmaxf(m0r, t0);
        const float mn1 = fmaxf(m1r, t1);
        const float al0 = __expf(m0r - mn0);
        const float al1 = __expf(m1r - mn1);
        m0r = mn0; m1r = mn1;

        float s0 = 0.f, s1 = 0.f;
#pragma unroll
        for (int nt = 0; nt < 8; nt++) {
            c[nt][0] = __expf(c[nt][0] - mn0);
            c[nt][1] = __expf(c[nt][1] - mn0);
            c[nt][2] = __expf(c[nt][2] - mn1);
            c[nt][3] = __expf(c[nt][3] - mn1);
            s0 += c[nt][0] + c[nt][1];
            s1 += c[nt][2] + c[nt][3];
        }
        s0 += __shfl_xor_sync(0xffffffffu, s0, 1);
        s0 += __shfl_xor_sync(0xffffffffu, s0, 2);
        s1 += __shfl_xor_sync(0xffffffffu, s1, 1);
        s1 += __shfl_xor_sync(0xffffffffu, s1, 2);
        l0r = l0r * al0 + s0;
        l1r = l1r * al1 + s1;

#pragma unroll
        for (int nt = 0; nt < 8; nt++) {
            o[nt][0] *= al0; o[nt][1] *= al0;
            o[nt][2] *= al1; o[nt][3] *= al1;
        }

        // ---- O += P V (P plain fp16, V plain -> 1 MMA per frag) ----------
#pragma unroll
        for (int kc = 0; kc < 4; kc++) {
            uint32_t ph[4];
            const float* p0 = c[2*kc];
            const float* p1 = c[2*kc+1];
            ph[0] = pack_h2(p0[0], p0[1]);
            ph[1] = pack_h2(p0[2], p0[3]);
            ph[2] = pack_h2(p1[0], p1[1]);
            ph[3] = pack_h2(p1[2], p1[3]);
#pragma unroll
            for (int ntp = 0; ntp < 4; ntp++) {
                const int row = kc * 16 + (grp & 1) * 8 + rr;
                const int ch  = ntp * 2 + (grp >> 1);
                const uint32_t off = fsw(row, ch);
                uint32_t v0, v1, v2, v3;
                ldsm4t(v0, v1, v2, v3, st + 16384u + off);
                mma_f16(o[2*ntp],   ph[0], ph[1], ph[2], ph[3], v0, v1);
                mma_f16(o[2*ntp+1], ph[0], ph[1], ph[2], ph[3], v2, v3);
            }
        }
        __syncthreads();     // all reads of this buffer done before refill
    }

    // ---- finalize + write plain fp16 [B,S,D] --------------------------------
    const float inv0 = 1.f / l0r;
    const float inv1 = 1.f / l1r;
    const int b = bh >> 4;
    const int h = bh & (H_ - 1);
    const int sq0 = mt * 64 + wid * 16 + (lane >> 2);
    const size_t base0 = ((size_t)(b * S_ + sq0)) * D_ + h * HD;
    const size_t base1 = base0 + (size_t)8 * D_;
#pragma unroll
    for (int nt = 0; nt < 8; nt++) {
        const int col = nt * 8 + (lane & 3) * 2;
        {
            __half2 hp = __floats2half2_rn(o[nt][0] * inv0, o[nt][1] * inv0);
            *(__half2*)(Oatt + base0 + col) = hp;
        }
        {
            __half2 hp = __floats2half2_rn(o[nt][2] * inv1, o[nt][3] * inv1);
            *(__half2*)(Oatt + base1 + col) = hp;
        }
    }
}

// ---------------- launch -----------------------------------------------------
extern "C" void kernel_launch(void* const* d_in, const int* in_sizes, int n_in,
                              void* d_out, int out_size)
{
    const float* x  = (const float*)d_in[0];
    float* out = (float*)d_out;

    void *pqh, *pql, *pkh, *pkl, *pv, *pxh, *pxl, *pwh, *pwl, *patt, *prope;
    cudaGetSymbolAddress(&pqh, g_qh);  cudaGetSymbolAddress(&pql, g_ql);
    cudaGetSymbolAddress(&pkh, g_kh);  cudaGetSymbolAddress(&pkl, g_kl);
    cudaGetSymbolAddress(&pv,  g_v);
    cudaGetSymbolAddress(&pxh, g_xh);  cudaGetSymbolAddress(&pxl, g_xl);
    cudaGetSymbolAddress(&pwh, g_wh);  cudaGetSymbolAddress(&pwl, g_wl);
    cudaGetSymbolAddress(&patt, g_att);
    cudaGetSymbolAddress(&prope, g_rope);

    cudaFuncSetAttribute(gemm_mma<1>, cudaFuncAttributeMaxDynamicSharedMemorySize, GSMEM);
    cudaFuncSetAttribute(gemm_mma<0>, cudaFuncAttributeMaxDynamicSharedMemorySize, GSMEM);
    cudaFuncSetAttribute(flash_mma, cudaFuncAttributeMaxDynamicSharedMemorySize, FSMEM);

    __half* xh = (__half*)pxh;
    __half* xl = (__half*)pxl;
    __half* wh = (__half*)pwh;
    __half* wl = (__half*)pwl;

    // RoPE table + fused splits
    rope_kernel<<<(S_ * 32 + 255) / 256, 256>>>((float2*)prope);
    split_all<<<(8 * RW) / 256, 256>>>(x, (const float*)d_in[1], (const float*)d_in[2],
                                       (const float*)d_in[3], (const float*)d_in[4],
                                       xh, xl, wh, wl);

    // fused QKV projection -> fp16 [B,H,S,hd] (Q,K hi/lo; V plain)
    dim3 qkvgrid(3 * D_ / 128, MTOT / 128);   // (24, 32)
    gemm_mma<1><<<qkvgrid, 256, GSMEM>>>(xh, xl, wh, wl, nullptr,
        (__half*)pqh, (__half*)pql, (__half*)pkh, (__half*)pkl, (__half*)pv);

    // tensor-core causal flash attention -> plain fp16 [B,S,D]
    dim3 agrid(S_ / 64, B_ * H_);        // (32, 32)
    flash_mma<<<agrid, 128, FSMEM>>>((const __half*)pqh, (const __half*)pql,
                                     (const __half*)pkh, (const __half*)pkl,
                                     (const __half*)pv,
                                     (__half*)patt);

    // output projection -> d_out (fp32), att plain x Wo plain (1 MMA)
    dim3 ogrid(D_ / 128, MTOT / 128);    // (8, 32)
    gemm_mma<0><<<ogrid, 256, GSMEM>>>((const __half*)patt, nullptr,
                                       wh + 3*(size_t)D_*D_, nullptr,
                                       out, nullptr, nullptr, nullptr, nullptr, nullptr);
}

// round 11
// speedup vs baseline: 1.3492x; 1.0715x over previous
#include <cuda_runtime.h>
#include <cuda_fp16.h>
#include <cstdint>
#include <math.h>

// ---------------- problem shape ----------------------------------------------
#define B_   2
#define S_   2048
#define D_   1024
#define H_   16
#define HD   64
#define MTOT (B_*S_)          // 4096
#define SCALE 0.125f          // 1/sqrt(64), exact power of two

// ---------------- baseline-PTX helpers (compile at compute_103) --------------
__device__ __forceinline__ uint32_t smem_u32(const void* p) {
    uint32_t a;
    asm("{ .reg .u64 t; cvta.to.shared.u64 t, %1; cvt.u32.u64 %0, t; }"
        : "=r"(a) : "l"(p));
    return a;
}
#define CP_ASYNC16(dst, src) \
    asm volatile("cp.async.cg.shared.global [%0], [%1], 16;" :: "r"(dst), "l"(src))
#define CP_COMMIT() asm volatile("cp.async.commit_group;" ::: "memory")
#define CP_WAIT2()  asm volatile("cp.async.wait_group 2;" ::: "memory")
#define CP_WAIT1()  asm volatile("cp.async.wait_group 1;" ::: "memory")
#define CP_WAIT0()  asm volatile("cp.async.wait_group 0;" ::: "memory")

__device__ __forceinline__ void ldsm4(uint32_t& r0, uint32_t& r1,
                                      uint32_t& r2, uint32_t& r3, uint32_t a) {
    asm volatile("ldmatrix.sync.aligned.m8n8.x4.shared.b16 {%0,%1,%2,%3}, [%4];"
                 : "=r"(r0), "=r"(r1), "=r"(r2), "=r"(r3) : "r"(a));
}
__device__ __forceinline__ void ldsm4t(uint32_t& r0, uint32_t& r1,
                                       uint32_t& r2, uint32_t& r3, uint32_t a) {
    asm volatile("ldmatrix.sync.aligned.m8n8.x4.trans.shared.b16 {%0,%1,%2,%3}, [%4];"
                 : "=r"(r0), "=r"(r1), "=r"(r2), "=r"(r3) : "r"(a));
}
__device__ __forceinline__ void mma_f16(float* c,
    uint32_t a0, uint32_t a1, uint32_t a2, uint32_t a3, uint32_t b0, uint32_t b1) {
    asm volatile("mma.sync.aligned.m16n8k16.row.col.f32.f16.f16.f32 "
                 "{%0,%1,%2,%3}, {%4,%5,%6,%7}, {%8,%9}, {%0,%1,%2,%3};"
                 : "+f"(c[0]), "+f"(c[1]), "+f"(c[2]), "+f"(c[3])
                 : "r"(a0), "r"(a1), "r"(a2), "r"(a3), "r"(b0), "r"(b1));
}
__device__ __forceinline__ uint32_t pack_h2(float a, float b) {
    __half2 t = __floats2half2_rn(a, b);     // x=a, y=b
    return *(uint32_t*)&t;
}

// ---------------- scratch (device globals; no allocations allowed) ----------
__device__ __half g_q [(size_t)B_*H_*S_*HD];                    // plain fp16
__device__ __half g_kh[(size_t)B_*H_*S_*HD], g_kl[(size_t)B_*H_*S_*HD];
__device__ __half g_v [(size_t)B_*H_*S_*HD];                    // plain fp16
__device__ __half g_xh[(size_t)MTOT*D_],  g_xl[(size_t)MTOT*D_];
__device__ __half g_wh[(size_t)4*D_*D_];                         // Wq|Wk|Wv|Wo
__device__ __half g_wl[(size_t)2*D_*D_];                         // Wq|Wk lo (Wk used)
__device__ __half g_att[(size_t)MTOT*D_];                        // attention out, plain
__device__ float2 g_rope[(size_t)S_*32];          // (cos,sin) per (spos, d/2)

// ---------------- RoPE table (exact sincosf, one-time) -----------------------
__global__ void rope_kernel(float2* __restrict__ t)
{
    int i = blockIdx.x * blockDim.x + threadIdx.x;    // over S_*32
    if (i >= S_ * 32) return;
    int spos = i >> 5, d2 = i & 31;
    float theta = powf(10000.0f, -2.0f * (float)d2 / (float)HD);
    float ang = (float)spos * theta;
    float ss, cc;
    sincosf(ang, &ss, &cc);
    t[i] = make_float2(cc, ss);
}

// ---------------- fused fp32 -> fp16 (hi[,lo]) split for x + 4 W -------------
#define RW  ((D_*D_)/4)        // 262144 float4 per weight
__global__ void split_all(const float* __restrict__ x,
                          const float* __restrict__ w0, const float* __restrict__ w1,
                          const float* __restrict__ w2, const float* __restrict__ w3,
                          __half* __restrict__ xh, __half* __restrict__ xl,
                          __half* __restrict__ wh, __half* __restrict__ wl)
{
    int i = blockIdx.x * blockDim.x + threadIdx.x;    // float4 index, 8*RW total
    const float* src;
    __half *hi, *lo;
    int local;
    if (i < 4 * RW) {
        src = x; hi = xh; lo = xl; local = i;
    } else {
        int ip = i - 4 * RW;
        int r  = ip >> 18;     // RW = 2^18
        local  = ip & (RW - 1);
        src = (r == 0) ? w0 : (r == 1) ? w1 : (r == 2) ? w2 : w3;
        hi = wh + (size_t)r * D_ * D_;
        lo = (r < 2) ? (wl + (size_t)r * D_ * D_) : nullptr;
    }
    float4 v = ((const float4*)src)[local];
    __half h0 = __float2half_rn(v.x);
    __half h1 = __float2half_rn(v.y);
    __half h2 = __float2half_rn(v.z);
    __half h3 = __float2half_rn(v.w);
    __half2 a, b;
    a.x = h0; a.y = h1; b.x = h2; b.y = h3;
    ((__half2*)hi)[2*local]   = a;
    ((__half2*)hi)[2*local+1] = b;
    if (lo) {
        a.x = __float2half_rn(v.x - __half2float(h0));
        a.y = __float2half_rn(v.y - __half2float(h1));
        b.x = __float2half_rn(v.z - __half2float(h2));
        b.y = __float2half_rn(v.w - __half2float(h3));
        ((__half2*)lo)[2*local]   = a;
        ((__half2*)lo)[2*local+1] = b;
    }
}

// ---------------- HMMA GEMM (3-stage): C[m,n] = sum_k A[m,k]*W[n,k] ----------
// MMA count per fragment: 1 + useAl + useBl (compensation terms).
#define BKG 32
#define NKI (D_/BKG)       // 32
#define STG 32768          // bytes per stage (Ah|Al|Bh|Bl, 8K each)
#define GSMEM (3*STG)      // 96 KB

__device__ __forceinline__ uint32_t sw_off(int row, int kc) {
    return (uint32_t)((row << 6) + ((kc ^ ((row >> 1) & 3)) << 4));
}

__device__ __forceinline__ void stage_load(
    uint32_t sb, int s, int k0, int tid, int m0, int n0, int useAl, int useBl,
    const __half* __restrict__ Ah, const __half* __restrict__ Al,
    const __half* __restrict__ Bh, const __half* __restrict__ Bl)
{
    const uint32_t base = sb + (uint32_t)s * STG;
#pragma unroll
    for (int p = 0; p < 2; p++) {
        const int gi  = tid + p * 256;
        const int row = gi >> 2;
        const int kc  = gi & 3;
        const uint32_t so = sw_off(row, kc);
        const size_t aoff = (size_t)(m0 + row) * D_ + k0 + kc * 8;
        const size_t boff = (size_t)(n0 + row) * D_ + k0 + kc * 8;
        CP_ASYNC16(base + 0     + so, Ah + aoff);
        if (useAl) CP_ASYNC16(base + 8192  + so, Al + aoff);
        CP_ASYNC16(base + 16384 + so, Bh + boff);
        if (useBl) CP_ASYNC16(base + 24576 + so, Bl + boff);
    }
}

// QKV=1: n0 in [0,3072): B = Wq|Wk|Wv rows; RoPE/scale + fp16 scatter.
//        Q: plain (1 MMA); K: x split + Wk split (3 MMAs, hi/lo out); V: plain.
// QKV=0: n0 in [0,1024): B = Wo rows, A = att plain (1 MMA); fp32 output.
template<int QKV>
__global__ __launch_bounds__(256, 1)
void gemm_mma(const __half* __restrict__ Ah, const __half* __restrict__ Al,
              const __half* __restrict__ Bh, const __half* __restrict__ Bl,
              float* __restrict__ Cf,
              __half* __restrict__ Qp,
              __half* __restrict__ Kh, __half* __restrict__ Kl,
              __half* __restrict__ Vp)
{
    extern __shared__ char smem[];
    const uint32_t sb = smem_u32(smem);
    const int tid  = threadIdx.x;
    const int wid  = tid >> 5;
    const int lane = tid & 31;
    const int m0 = blockIdx.y * 128;
    const int n0 = blockIdx.x * 128;
    const int wm = (wid & 1) * 64;
    const int wn = (wid >> 1) * 32;
    const int w  = QKV ? (n0 >> 10) : 3;
    const int useAl = QKV ? (w == 1) : 0;    // x compensation only for K
    const int useBl = QKV ? (w == 1) : 0;    // W compensation only for Wk

    float acc[4][4][4];
#pragma unroll
    for (int a = 0; a < 4; a++)
#pragma unroll
        for (int b = 0; b < 4; b++)
#pragma unroll
            for (int c = 0; c < 4; c++) acc[a][b][c] = 0.f;

    stage_load(sb, 0, 0, tid, m0, n0, useAl, useBl, Ah, Al, Bh, Bl);
    CP_COMMIT();
    stage_load(sb, 1, BKG, tid, m0, n0, useAl, useBl, Ah, Al, Bh, Bl);
    CP_COMMIT();

    const int g = lane >> 3;
    const int r = lane & 7;

    for (int i = 0; i < NKI; i++) {
        if (i + 2 < NKI) {
            int s = i + 2; while (s >= 3) s -= 3;
            stage_load(sb, s, (i + 2) * BKG, tid, m0, n0, useAl, useBl, Ah, Al, Bh, Bl);
            CP_COMMIT();
            CP_WAIT2();
        } else if (i + 1 < NKI) {
            CP_WAIT1();
        } else {
            CP_WAIT0();
        }
        __syncthreads();     // cross-thread visibility of stage i's cp.asyncs
        int cs = i; while (cs >= 3) cs -= 3;
        const uint32_t base = sb + (uint32_t)cs * STG;
#pragma unroll
        for (int h = 0; h < 2; h++) {
            uint32_t ah[4][4], al[4][4], bhf[2][4], blf[2][4];
#pragma unroll
            for (int mi = 0; mi < 4; mi++) {
                const int arow = wm + mi * 16 + (g & 1) * 8 + r;
                const int akc  = h * 2 + (g >> 1);
                const uint32_t so = sw_off(arow, akc);
                ldsm4(ah[mi][0], ah[mi][1], ah[mi][2], ah[mi][3], base + 0 + so);
                if (useAl)
                    ldsm4(al[mi][0], al[mi][1], al[mi][2], al[mi][3], base + 8192 + so);
            }
#pragma unroll
            for (int ng = 0; ng < 2; ng++) {
                const int brow = wn + ng * 16 + (g >> 1) * 8 + r;
                const int bkc  = h * 2 + (g & 1);
                const uint32_t so = sw_off(brow, bkc);
                ldsm4(bhf[ng][0], bhf[ng][1], bhf[ng][2], bhf[ng][3], base + 16384 + so);
                if (useBl)
                    ldsm4(blf[ng][0], blf[ng][1], blf[ng][2], blf[ng][3], base + 24576 + so);
            }
#pragma unroll
            for (int mi = 0; mi < 4; mi++)
#pragma unroll
                for (int ni = 0; ni < 4; ni++) {
                    const uint32_t* bh = &bhf[ni >> 1][(ni & 1) * 2];
                    mma_f16(acc[mi][ni], ah[mi][0], ah[mi][1], ah[mi][2], ah[mi][3], bh[0], bh[1]);
                    if (useAl)
                        mma_f16(acc[mi][ni], al[mi][0], al[mi][1], al[mi][2], al[mi][3], bh[0], bh[1]);
                    if (useBl) {
                        const uint32_t* bl = &blf[ni >> 1][(ni & 1) * 2];
                        mma_f16(acc[mi][ni], ah[mi][0], ah[mi][1], ah[mi][2], ah[mi][3], bl[0], bl[1]);
                    }
                }
        }
        __syncthreads();     // all reads of this stage done before refill
    }

    // ---------------- epilogue ------------------------------------------------
    const int tg = lane >> 2;
    const int tq = lane & 3;
#pragma unroll
    for (int mi = 0; mi < 4; mi++) {
#pragma unroll
        for (int hf = 0; hf < 2; hf++) {
            const int m    = m0 + wm + mi * 16 + hf * 8 + tg;
            const int spos = m & (S_ - 1);
            const int bb   = m >> 11;
#pragma unroll
            for (int ni = 0; ni < 4; ni++) {
                const int n = n0 + wn + ni * 8 + tq * 2;     // even (global)
                float v1 = acc[mi][ni][hf * 2 + 0];
                float v2 = acc[mi][ni][hf * 2 + 1];
                if (QKV) {
                    const int nl = n & 1023;
                    const int d  = nl & (HD - 1);
                    if (w < 2) {
                        float2 cs = g_rope[spos * 32 + (d >> 1)];
                        float y1 = v1 * cs.x - v2 * cs.y;
                        float y2 = v1 * cs.y + v2 * cs.x;
                        v1 = y1; v2 = y2;
                    }
                    if (w == 0) { v1 *= SCALE; v2 *= SCALE; }
                    const int hh = nl >> 6;
                    const size_t idx = (((size_t)(bb * H_ + hh) * S_) + spos) * HD + d;
                    __half h1 = __float2half_rn(v1);
                    __half h2 = __float2half_rn(v2);
                    __half2 hp; hp.x = h1; hp.y = h2;
                    if (w == 1) {
                        __half2 lp;
                        lp.x = __float2half_rn(v1 - __half2float(h1));
                        lp.y = __float2half_rn(v2 - __half2float(h2));
                        *(__half2*)(Kh + idx) = hp;
                        *(__half2*)(Kl + idx) = lp;
                    } else {
                        __half* C = (w == 0) ? Qp : Vp;
                        *(__half2*)(C + idx) = hp;           // plain fp16
                    }
                } else {
                    float* p = Cf + (size_t)m * D_ + n;
                    *(float2*)p = make_float2(v1, v2);
                }
            }
        }
    }
}

// ---------------- HMMA flash attention (causal), fp16 -----------------------
// 128 threads (4 warps), Q tile 64 rows, K/V tiles 64 rows, double-buffered.
// QK: q plain x (kh+kl) -> 2 MMAs; PV: P plain x V plain -> 1 MMA.
// Stage = KH|KL|V (8K each) = 24KB; Q staged through stage-0; smem 48KB.
#define FSTG    24576u
#define FSMEM   (2*24576)

__device__ __forceinline__ uint32_t fsw(int row, int c) {   // 128B rows
    return (uint32_t)(row * 128 + ((c ^ (row & 7)) << 4));
}

__device__ __forceinline__ void fa_stage(
    uint32_t base, const __half* kh, const __half* kl,
    const __half* v, int s0, int tid)
{
#pragma unroll
    for (int p = 0; p < 4; p++) {
        const int gi  = tid + p * 128;       // 0..511
        const int row = gi >> 3;
        const int c   = gi & 7;
        const uint32_t off = fsw(row, c);
        const size_t g = (size_t)(s0 + row) * HD + c * 8;
        CP_ASYNC16(base + 0u     + off, kh + g);
        CP_ASYNC16(base + 8192u  + off, kl + g);
        CP_ASYNC16(base + 16384u + off, v + g);
    }
}

__global__ __launch_bounds__(128, 2)
void flash_mma(const __half* __restrict__ Q,
               const __half* __restrict__ Kh, const __half* __restrict__ Kl,
               const __half* __restrict__ V,
               __half* __restrict__ Oatt)
{
    extern __shared__ char smem[];
    const uint32_t sb = smem_u32(smem);
    const int tid  = threadIdx.x;
    const int wid  = tid >> 5;
    const int lane = tid & 31;
    const int bh = blockIdx.y;
    const int mt = (int)gridDim.x - 1 - (int)blockIdx.x;   // big tiles first
    const int nkt = mt + 1;                                // 64-row K tiles

    const __half* qb_  = Q  + ((size_t)bh * S_) * HD;
    const __half* khb_ = Kh + ((size_t)bh * S_) * HD;
    const __half* klb_ = Kl + ((size_t)bh * S_) * HD;
    const __half* vb_  = V  + ((size_t)bh * S_) * HD;

    const int grp = lane >> 3;
    const int rr  = lane & 7;

    // ---- stage Q (plain) through stage-0 buffer, extract frags -------------
#pragma unroll
    for (int p = 0; p < 4; p++) {
        const int gi  = tid + p * 128;       // 0..511
        const int row = gi >> 3;
        const int c   = gi & 7;
        const uint32_t off = fsw(row, c);
        const size_t g = (size_t)(mt * 64 + row) * HD + c * 8;
        CP_ASYNC16(sb + off, qb_ + g);
    }
    CP_COMMIT();
    CP_WAIT0();
    __syncthreads();

    uint32_t qf[4][4];
#pragma unroll
    for (int kc = 0; kc < 4; kc++) {
        const int row = wid * 16 + (grp & 1) * 8 + rr;
        const int c   = kc * 2 + (grp >> 1);
        const uint32_t off = fsw(row, c);
        ldsm4(qf[kc][0], qf[kc][1], qf[kc][2], qf[kc][3], sb + off);
    }
    __syncthreads();     // Q frags extracted before stage-0 is overwritten

    fa_stage(sb, khb_, klb_, vb_, 0, tid);
    CP_COMMIT();

    float o[8][4];
#pragma unroll
    for (int a = 0; a < 8; a++)
#pragma unroll
        for (int b = 0; b < 4; b++) o[a][b] = 0.f;
    float m0r = -1e30f, m1r = -1e30f, l0r = 0.f, l1r = 0.f;

    for (int kt = 0; kt < nkt; kt++) {
        if (kt + 1 < nkt) {
            fa_stage(sb + (uint32_t)((kt + 1) & 1) * FSTG,
                     khb_, klb_, vb_, (kt + 1) * 64, tid);
            CP_COMMIT();
            CP_WAIT1();
        } else {
            CP_WAIT0();
        }
        __syncthreads();     // stage kt visible to all threads

        const uint32_t st = sb + (uint32_t)(kt & 1) * FSTG;

        // ---- scores S = Q (Kh + Kl)^T : 2 MMAs per kc --------------------
        float c[8][4];
#pragma unroll
        for (int a = 0; a < 8; a++)
#pragma unroll
            for (int b = 0; b < 4; b++) c[a][b] = 0.f;

#pragma unroll
        for (int nt = 0; nt < 8; nt++) {
            const int j = nt * 8 + rr;
            uint32_t kb0[4], kb1[4], lb0[4], lb1[4];
            ldsm4(kb0[0], kb0[1], kb0[2], kb0[3], st + 0u    + fsw(j, 0 + grp));
            ldsm4(kb1[0], kb1[1], kb1[2], kb1[3], st + 0u    + fsw(j, 4 + grp));
            ldsm4(lb0[0], lb0[1], lb0[2], lb0[3], st + 8192u + fsw(j, 0 + grp));
            ldsm4(lb1[0], lb1[1], lb1[2], lb1[3], st + 8192u + fsw(j, 4 + grp));
            mma_f16(c[nt], qf[0][0], qf[0][1], qf[0][2], qf[0][3], kb0[0], kb0[1]);
            mma_f16(c[nt], qf[0][0], qf[0][1], qf[0][2], qf[0][3], lb0[0], lb0[1]);
            mma_f16(c[nt], qf[1][0], qf[1][1], qf[1][2], qf[1][3], kb0[2], kb0[3]);
            mma_f16(c[nt], qf[1][0], qf[1][1], qf[1][2], qf[1][3], lb0[2], lb0[3]);
            mma_f16(c[nt], qf[2][0], qf[2][1], qf[2][2], qf[2][3], kb1[0], kb1[1]);
            mma_f16(c[nt], qf[2][0], qf[2][1], qf[2][2], qf[2][3], lb1[0], lb1[1]);
            mma_f16(c[nt], qf[3][0], qf[3][1], qf[3][2], qf[3][3], kb1[2], kb1[3]);
            mma_f16(c[nt], qf[3][0], qf[3][1], qf[3][2], qf[3][3], lb1[2], lb1[3]);
        }

        // ---- causal mask on diagonal tile --------------------------------
        if (kt == mt) {
            const int i0 = wid * 16 + (lane >> 2);
#pragma unroll
            for (int nt = 0; nt < 8; nt++) {
                const int j0 = nt * 8 + (lane & 3) * 2;
                if (j0     > i0)     c[nt][0] = -1e30f;
                if (j0 + 1 > i0)     c[nt][1] = -1e30f;
                if (j0     > i0 + 8) c[nt][2] = -1e30f;
                if (j0 + 1 > i0 + 8) c[nt][3] = -1e30f;
            }
        }

        // ---- online softmax ----------------------------------------------
        float t0 = -1e30f, t1 = -1e30f;
#pragma unroll
        for (int nt = 0; nt < 8; nt++) {
            t0 = fmaxf(t0, fmaxf(c[nt][0], c[nt][1]));
            t1 = fmaxf(t1, fmaxf(c[nt][2], c[nt][3]));
        }
        t0 = fmaxf(t0, __shfl_xor_sync(0xffffffffu, t0, 1));
        t0 = fmaxf(t0, __shfl_xor_sync(0xffffffffu, t0, 2));
        t1 = fmaxf(t1, __shfl_xor_sync(0xffffffffu, t1, 1));
        t1 = fmaxf(t1, __shfl_xor_sync(0xffffffffu, t1, 2));
        const float mn0 = fmaxf(m0r, t0);
        const float mn1 = fmaxf(m1r, t1);
        const float al0 = __expf(m0r - mn0);
        const float al1 = __expf(m1r - mn1);
        m0r = mn0; m1r = mn1;

        float s0 = 0.f, s1 = 0.f;
#pragma unroll
        for (int nt = 0; nt < 8; nt++) {
            c[nt][0] = __expf(c[nt][0] - mn0);
            c[nt][1] = __expf(c[nt][1] - mn0);
            c[nt][2] = __expf(c[nt][2] - mn1);
            c[nt][3] = __expf(c[nt][3] - mn1);
            s0 += c[nt][0] + c[nt][1];
            s1 += c[nt][2] + c[nt][3];
        }
        s0 += __shfl_xor_sync(0xffffffffu, s0, 1);
        s0 += __shfl_xor_sync(0xffffffffu, s0, 2);
        s1 += __shfl_xor_sync(0xffffffffu, s1, 1);
        s1 += __shfl_xor_sync(0xffffffffu, s1, 2);
        l0r = l0r * al0 + s0;
        l1r = l1r * al1 + s1;

#pragma unroll
        for (int nt = 0; nt < 8; nt++) {
            o[nt][0] *= al0; o[nt][1] *= al0;
            o[nt][2] *= al1; o[nt][3] *= al1;
        }

        // ---- O += P V (P plain fp16, V plain -> 1 MMA per frag) ----------
#pragma unroll
        for (int kc = 0; kc < 4; kc++) {
            uint32_t ph[4];
            const float* p0 = c[2*kc];
            const float* p1 = c[2*kc+1];
            ph[0] = pack_h2(p0[0], p0[1]);
            ph[1] = pack_h2(p0[2], p0[3]);
            ph[2] = pack_h2(p1[0], p1[1]);
            ph[3] = pack_h2(p1[2], p1[3]);
#pragma unroll
            for (int ntp = 0; ntp < 4; ntp++) {
                const int row = kc * 16 + (grp & 1) * 8 + rr;
                const int ch  = ntp * 2 + (grp >> 1);
                const uint32_t off = fsw(row, ch);
                uint32_t v0, v1, v2, v3;
                ldsm4t(v0, v1, v2, v3, st + 16384u + off);
                mma_f16(o[2*ntp],   ph[0], ph[1], ph[2], ph[3], v0, v1);
                mma_f16(o[2*ntp+1], ph[0], ph[1], ph[2], ph[3], v2, v3);
            }
        }
        __syncthreads();     // all reads of this buffer done before refill
    }

    // ---- finalize + write plain fp16 [B,S,D] --------------------------------
    const float inv0 = 1.f / l0r;
    const float inv1 = 1.f / l1r;
    const int b = bh >> 4;
    const int h = bh & (H_ - 1);
    const int sq0 = mt * 64 + wid * 16 + (lane >> 2);
    const size_t base0 = ((size_t)(b * S_ + sq0)) * D_ + h * HD;
    const size_t base1 = base0 + (size_t)8 * D_;
#pragma unroll
    for (int nt = 0; nt < 8; nt++) {
        const int col = nt * 8 + (lane & 3) * 2;
        {
            __half2 hp = __floats2half2_rn(o[nt][0] * inv0, o[nt][1] * inv0);
            *(__half2*)(Oatt + base0 + col) = hp;
        }
        {
            __half2 hp = __floats2half2_rn(o[nt][2] * inv1, o[nt][3] * inv1);
            *(__half2*)(Oatt + base1 + col) = hp;
        }
    }
}

// ---------------- launch -----------------------------------------------------
extern "C" void kernel_launch(void* const* d_in, const int* in_sizes, int n_in,
                              void* d_out, int out_size)
{
    const float* x  = (const float*)d_in[0];
    float* out = (float*)d_out;

    void *pq, *pkh, *pkl, *pv, *pxh, *pxl, *pwh, *pwl, *patt, *prope;
    cudaGetSymbolAddress(&pq,  g_q);
    cudaGetSymbolAddress(&pkh, g_kh);  cudaGetSymbolAddress(&pkl, g_kl);
    cudaGetSymbolAddress(&pv,  g_v);
    cudaGetSymbolAddress(&pxh, g_xh);  cudaGetSymbolAddress(&pxl, g_xl);
    cudaGetSymbolAddress(&pwh, g_wh);  cudaGetSymbolAddress(&pwl, g_wl);
    cudaGetSymbolAddress(&patt, g_att);
    cudaGetSymbolAddress(&prope, g_rope);

    cudaFuncSetAttribute(gemm_mma<1>, cudaFuncAttributeMaxDynamicSharedMemorySize, GSMEM);
    cudaFuncSetAttribute(gemm_mma<0>, cudaFuncAttributeMaxDynamicSharedMemorySize, GSMEM);
    cudaFuncSetAttribute(flash_mma, cudaFuncAttributeMaxDynamicSharedMemorySize, FSMEM);

    __half* xh = (__half*)pxh;
    __half* xl = (__half*)pxl;
    __half* wh = (__half*)pwh;
    __half* wl = (__half*)pwl;

    // RoPE table + fused splits
    rope_kernel<<<(S_ * 32 + 255) / 256, 256>>>((float2*)prope);
    split_all<<<(8 * RW) / 256, 256>>>(x, (const float*)d_in[1], (const float*)d_in[2],
                                       (const float*)d_in[3], (const float*)d_in[4],
                                       xh, xl, wh, wl);

    // fused QKV projection -> fp16 [B,H,S,hd] (Q plain, K hi/lo, V plain)
    dim3 qkvgrid(3 * D_ / 128, MTOT / 128);   // (24, 32)
    gemm_mma<1><<<qkvgrid, 256, GSMEM>>>(xh, xl, wh, wl, nullptr,
        (__half*)pq, (__half*)pkh, (__half*)pkl, (__half*)pv);

    // tensor-core causal flash attention -> plain fp16 [B,S,D]
    dim3 agrid(S_ / 64, B_ * H_);        // (32, 32)
    flash_mma<<<agrid, 128, FSMEM>>>((const __half*)pq,
                                     (const __half*)pkh, (const __half*)pkl,
                                     (const __half*)pv,
                                     (__half*)patt);

    // output projection -> d_out (fp32), att plain x Wo plain (1 MMA)
    dim3 ogrid(D_ / 128, MTOT / 128);    // (8, 32)
    gemm_mma<0><<<ogrid, 256, GSMEM>>>((const __half*)patt, nullptr,
                                       wh + 3*(size_t)D_*D_, nullptr,
                                       out, nullptr, nullptr, nullptr, nullptr);
}

// round 12
// speedup vs baseline: 1.6068x; 1.1909x over previous
#include <cuda_runtime.h>
#include <cuda_fp16.h>
#include <cstdint>
#include <math.h>

// ---------------- problem shape ----------------------------------------------
#define B_   2
#define S_   2048
#define D_   1024
#define H_   16
#define HD   64
#define MTOT (B_*S_)          // 4096
#define SCALE 0.125f          // 1/sqrt(64), exact power of two

// ---------------- baseline-PTX helpers (compile at compute_103) --------------
__device__ __forceinline__ uint32_t smem_u32(const void* p) {
    uint32_t a;
    asm("{ .reg .u64 t; cvta.to.shared.u64 t, %1; cvt.u32.u64 %0, t; }"
        : "=r"(a) : "l"(p));
    return a;
}
#define CP_ASYNC16(dst, src) \
    asm volatile("cp.async.cg.shared.global [%0], [%1], 16;" :: "r"(dst), "l"(src))
#define CP_COMMIT() asm volatile("cp.async.commit_group;" ::: "memory")
#define CP_WAIT2()  asm volatile("cp.async.wait_group 2;" ::: "memory")
#define CP_WAIT1()  asm volatile("cp.async.wait_group 1;" ::: "memory")
#define CP_WAIT0()  asm volatile("cp.async.wait_group 0;" ::: "memory")

__device__ __forceinline__ void ldsm4(uint32_t& r0, uint32_t& r1,
                                      uint32_t& r2, uint32_t& r3, uint32_t a) {
    asm volatile("ldmatrix.sync.aligned.m8n8.x4.shared.b16 {%0,%1,%2,%3}, [%4];"
                 : "=r"(r0), "=r"(r1), "=r"(r2), "=r"(r3) : "r"(a));
}
__device__ __forceinline__ void ldsm4t(uint32_t& r0, uint32_t& r1,
                                       uint32_t& r2, uint32_t& r3, uint32_t a) {
    asm volatile("ldmatrix.sync.aligned.m8n8.x4.trans.shared.b16 {%0,%1,%2,%3}, [%4];"
                 : "=r"(r0), "=r"(r1), "=r"(r2), "=r"(r3) : "r"(a));
}
__device__ __forceinline__ void mma_f16(float* c,
    uint32_t a0, uint32_t a1, uint32_t a2, uint32_t a3, uint32_t b0, uint32_t b1) {
    asm volatile("mma.sync.aligned.m16n8k16.row.col.f32.f16.f16.f32 "
                 "{%0,%1,%2,%3}, {%4,%5,%6,%7}, {%8,%9}, {%0,%1,%2,%3};"
                 : "+f"(c[0]), "+f"(c[1]), "+f"(c[2]), "+f"(c[3])
                 : "r"(a0), "r"(a1), "r"(a2), "r"(a3), "r"(b0), "r"(b1));
}
__device__ __forceinline__ uint32_t pack_h2(float a, float b) {
    __half2 t = __floats2half2_rn(a, b);     // x=a, y=b
    return *(uint32_t*)&t;
}

// ---------------- scratch (device globals; no allocations allowed) ----------
__device__ __half g_q  [(size_t)B_*H_*S_*HD];
__device__ __half g_k  [(size_t)B_*H_*S_*HD];
__device__ __half g_v  [(size_t)B_*H_*S_*HD];
__device__ __half g_xh [(size_t)MTOT*D_];
__device__ __half g_wh [(size_t)4*D_*D_];                        // Wq|Wk|Wv|Wo
__device__ __half g_att[(size_t)MTOT*D_];
__device__ float2 g_rope[(size_t)S_*32];          // (cos,sin) per (spos, d/2)

// ---------------- RoPE table (exact sincosf, one-time) -----------------------
__global__ void rope_kernel(float2* __restrict__ t)
{
    int i = blockIdx.x * blockDim.x + threadIdx.x;    // over S_*32
    if (i >= S_ * 32) return;
    int spos = i >> 5, d2 = i & 31;
    float theta = powf(10000.0f, -2.0f * (float)d2 / (float)HD);
    float ang = (float)spos * theta;
    float ss, cc;
    sincosf(ang, &ss, &cc);
    t[i] = make_float2(cc, ss);
}

// ---------------- fused fp32 -> fp16 convert for x + 4 W ---------------------
#define RW  ((D_*D_)/4)        // 262144 float4 per weight
__global__ void split_all(const float* __restrict__ x,
                          const float* __restrict__ w0, const float* __restrict__ w1,
                          const float* __restrict__ w2, const float* __restrict__ w3,
                          __half* __restrict__ xh, __half* __restrict__ wh)
{
    int i = blockIdx.x * blockDim.x + threadIdx.x;    // float4 index, 8*RW total
    const float* src;
    __half* hi;
    int local;
    if (i < 4 * RW) {
        src = x; hi = xh; local = i;
    } else {
        int ip = i - 4 * RW;
        int r  = ip >> 18;     // RW = 2^18
        local  = ip & (RW - 1);
        src = (r == 0) ? w0 : (r == 1) ? w1 : (r == 2) ? w2 : w3;
        hi = wh + (size_t)r * D_ * D_;
    }
    float4 v = ((const float4*)src)[local];
    __half2 a = __floats2half2_rn(v.x, v.y);
    __half2 b = __floats2half2_rn(v.z, v.w);
    ((__half2*)hi)[2*local]   = a;
    ((__half2*)hi)[2*local+1] = b;
}

// ---------------- HMMA GEMM (3-stage): C[m,n] = sum_k A[m,k]*W[n,k] ----------
// Plain fp16, 1 MMA per fragment. Stage = Ah(8K)|Bh(8K) = 16KB, 3 stages =
// 48KB -> 2 CTAs/SM for cross-CTA pipeline overlap.
#define BKG 32
#define NKI (D_/BKG)       // 32
#define STG 16384          // bytes per stage
#define GSMEM (3*STG)      // 48 KB

__device__ __forceinline__ uint32_t sw_off(int row, int kc) {
    return (uint32_t)((row << 6) + ((kc ^ ((row >> 1) & 3)) << 4));
}

__device__ __forceinline__ void stage_load(
    uint32_t sb, int s, int k0, int tid, int m0, int n0,
    const __half* __restrict__ A, const __half* __restrict__ B)
{
    const uint32_t base = sb + (uint32_t)s * STG;
#pragma unroll
    for (int p = 0; p < 2; p++) {
        const int gi  = tid + p * 256;
        const int row = gi >> 2;
        const int kc  = gi & 3;
        const uint32_t so = sw_off(row, kc);
        CP_ASYNC16(base + 0    + so, A + (size_t)(m0 + row) * D_ + k0 + kc * 8);
        CP_ASYNC16(base + 8192 + so, B + (size_t)(n0 + row) * D_ + k0 + kc * 8);
    }
}

// QKV=1: n0 in [0,3072): B = Wq|Wk|Wv rows; RoPE/scale + fp16 scatter.
// QKV=0: n0 in [0,1024): B = Wo rows; fp32 [M,D] output.
template<int QKV>
__global__ __launch_bounds__(256, 2)
void gemm_mma(const __half* __restrict__ A, const __half* __restrict__ B,
              float* __restrict__ Cf,
              __half* __restrict__ Qp, __half* __restrict__ Kp,
              __half* __restrict__ Vp)
{
    extern __shared__ char smem[];
    const uint32_t sb = smem_u32(smem);
    const int tid  = threadIdx.x;
    const int wid  = tid >> 5;
    const int lane = tid & 31;
    const int m0 = blockIdx.y * 128;
    const int n0 = blockIdx.x * 128;
    const int wm = (wid & 1) * 64;
    const int wn = (wid >> 1) * 32;
    const int w  = QKV ? (n0 >> 10) : 3;

    float acc[4][4][4];
#pragma unroll
    for (int a = 0; a < 4; a++)
#pragma unroll
        for (int b = 0; b < 4; b++)
#pragma unroll
            for (int c = 0; c < 4; c++) acc[a][b][c] = 0.f;

    stage_load(sb, 0, 0, tid, m0, n0, A, B);
    CP_COMMIT();
    stage_load(sb, 1, BKG, tid, m0, n0, A, B);
    CP_COMMIT();

    const int g = lane >> 3;
    const int r = lane & 7;

    for (int i = 0; i < NKI; i++) {
        if (i + 2 < NKI) {
            int s = i + 2; while (s >= 3) s -= 3;
            stage_load(sb, s, (i + 2) * BKG, tid, m0, n0, A, B);
            CP_COMMIT();
            CP_WAIT2();
        } else if (i + 1 < NKI) {
            CP_WAIT1();
        } else {
            CP_WAIT0();
        }
        __syncthreads();     // cross-thread visibility of stage i's cp.asyncs
        int cs = i; while (cs >= 3) cs -= 3;
        const uint32_t base = sb + (uint32_t)cs * STG;
#pragma unroll
        for (int h = 0; h < 2; h++) {
            uint32_t ah[4][4], bhf[2][4];
#pragma unroll
            for (int mi = 0; mi < 4; mi++) {
                const int arow = wm + mi * 16 + (g & 1) * 8 + r;
                const int akc  = h * 2 + (g >> 1);
                ldsm4(ah[mi][0], ah[mi][1], ah[mi][2], ah[mi][3],
                      base + 0 + sw_off(arow, akc));
            }
#pragma unroll
            for (int ng = 0; ng < 2; ng++) {
                const int brow = wn + ng * 16 + (g >> 1) * 8 + r;
                const int bkc  = h * 2 + (g & 1);
                ldsm4(bhf[ng][0], bhf[ng][1], bhf[ng][2], bhf[ng][3],
                      base + 8192 + sw_off(brow, bkc));
            }
#pragma unroll
            for (int mi = 0; mi < 4; mi++)
#pragma unroll
                for (int ni = 0; ni < 4; ni++) {
                    const uint32_t* bh = &bhf[ni >> 1][(ni & 1) * 2];
                    mma_f16(acc[mi][ni], ah[mi][0], ah[mi][1], ah[mi][2], ah[mi][3], bh[0], bh[1]);
                }
        }
        __syncthreads();     // all reads of this stage done before refill
    }

    // ---------------- epilogue ------------------------------------------------
    const int tg = lane >> 2;
    const int tq = lane & 3;
#pragma unroll
    for (int mi = 0; mi < 4; mi++) {
#pragma unroll
        for (int hf = 0; hf < 2; hf++) {
            const int m    = m0 + wm + mi * 16 + hf * 8 + tg;
            const int spos = m & (S_ - 1);
            const int bb   = m >> 11;
#pragma unroll
            for (int ni = 0; ni < 4; ni++) {
                const int n = n0 + wn + ni * 8 + tq * 2;     // even (global)
                float v1 = acc[mi][ni][hf * 2 + 0];
                float v2 = acc[mi][ni][hf * 2 + 1];
                if (QKV) {
                    const int nl = n & 1023;
                    const int d  = nl & (HD - 1);
                    if (w < 2) {
                        float2 cs = g_rope[spos * 32 + (d >> 1)];
                        float y1 = v1 * cs.x - v2 * cs.y;
                        float y2 = v1 * cs.y + v2 * cs.x;
                        v1 = y1; v2 = y2;
                    }
                    if (w == 0) { v1 *= SCALE; v2 *= SCALE; }
                    const int hh = nl >> 6;
                    const size_t idx = (((size_t)(bb * H_ + hh) * S_) + spos) * HD + d;
                    __half2 hp = __floats2half2_rn(v1, v2);
                    __half* C = (w == 0) ? Qp : (w == 1) ? Kp : Vp;
                    *(__half2*)(C + idx) = hp;
                } else {
                    float* p = Cf + (size_t)m * D_ + n;
                    *(float2*)p = make_float2(v1, v2);
                }
            }
        }
    }
}

// ---------------- HMMA flash attention (causal), plain fp16 ------------------
// 128 threads (4 warps), Q tile 64 rows, K/V tiles 64 rows, double-buffered.
// QK: 1 MMA per kc; PV: 1 MMA per frag. Stage = K(8K)|V(8K) = 16KB; Q staged
// through stage-0; smem 32KB; __launch_bounds__(128,3) -> 3 CTAs/SM.
#define FSTG    16384u
#define FSMEM   (2*16384)

__device__ __forceinline__ uint32_t fsw(int row, int c) {   // 128B rows
    return (uint32_t)(row * 128 + ((c ^ (row & 7)) << 4));
}

__device__ __forceinline__ void fa_stage(
    uint32_t base, const __half* k, const __half* v, int s0, int tid)
{
#pragma unroll
    for (int p = 0; p < 4; p++) {
        const int gi  = tid + p * 128;       // 0..511
        const int row = gi >> 3;
        const int c   = gi & 7;
        const uint32_t off = fsw(row, c);
        const size_t g = (size_t)(s0 + row) * HD + c * 8;
        CP_ASYNC16(base + 0u    + off, k + g);
        CP_ASYNC16(base + 8192u + off, v + g);
    }
}

__global__ __launch_bounds__(128, 3)
void flash_mma(const __half* __restrict__ Q, const __half* __restrict__ K,
               const __half* __restrict__ V, __half* __restrict__ Oatt)
{
    extern __shared__ char smem[];
    const uint32_t sb = smem_u32(smem);
    const int tid  = threadIdx.x;
    const int wid  = tid >> 5;
    const int lane = tid & 31;
    const int bh = blockIdx.y;
    const int mt = (int)gridDim.x - 1 - (int)blockIdx.x;   // big tiles first
    const int nkt = mt + 1;                                // 64-row K tiles

    const __half* qb_ = Q + ((size_t)bh * S_) * HD;
    const __half* kb_ = K + ((size_t)bh * S_) * HD;
    const __half* vb_ = V + ((size_t)bh * S_) * HD;

    const int grp = lane >> 3;
    const int rr  = lane & 7;

    // ---- stage Q (plain) through stage-0 buffer, extract frags -------------
#pragma unroll
    for (int p = 0; p < 4; p++) {
        const int gi  = tid + p * 128;       // 0..511
        const int row = gi >> 3;
        const int c   = gi & 7;
        const uint32_t off = fsw(row, c);
        CP_ASYNC16(sb + off, qb_ + (size_t)(mt * 64 + row) * HD + c * 8);
    }
    CP_COMMIT();
    CP_WAIT0();
    __syncthreads();

    uint32_t qf[4][4];
#pragma unroll
    for (int kc = 0; kc < 4; kc++) {
        const int row = wid * 16 + (grp & 1) * 8 + rr;
        const int c   = kc * 2 + (grp >> 1);
        ldsm4(qf[kc][0], qf[kc][1], qf[kc][2], qf[kc][3], sb + fsw(row, c));
    }
    __syncthreads();     // Q frags extracted before stage-0 is overwritten

    fa_stage(sb, kb_, vb_, 0, tid);
    CP_COMMIT();

    float o[8][4];
#pragma unroll
    for (int a = 0; a < 8; a++)
#pragma unroll
        for (int b = 0; b < 4; b++) o[a][b] = 0.f;
    float m0r = -1e30f, m1r = -1e30f, l0r = 0.f, l1r = 0.f;

    for (int kt = 0; kt < nkt; kt++) {
        if (kt + 1 < nkt) {
            fa_stage(sb + (uint32_t)((kt + 1) & 1) * FSTG,
                     kb_, vb_, (kt + 1) * 64, tid);
            CP_COMMIT();
            CP_WAIT1();
        } else {
            CP_WAIT0();
        }
        __syncthreads();     // stage kt visible to all threads

        const uint32_t st = sb + (uint32_t)(kt & 1) * FSTG;

        // ---- scores S = Q K^T : 1 MMA per kc -----------------------------
        float c[8][4];
#pragma unroll
        for (int a = 0; a < 8; a++)
#pragma unroll
            for (int b = 0; b < 4; b++) c[a][b] = 0.f;

#pragma unroll
        for (int nt = 0; nt < 8; nt++) {
            const int j = nt * 8 + rr;
            uint32_t kb0[4], kb1[4];
            ldsm4(kb0[0], kb0[1], kb0[2], kb0[3], st + fsw(j, 0 + grp));
            ldsm4(kb1[0], kb1[1], kb1[2], kb1[3], st + fsw(j, 4 + grp));
            mma_f16(c[nt], qf[0][0], qf[0][1], qf[0][2], qf[0][3], kb0[0], kb0[1]);
            mma_f16(c[nt], qf[1][0], qf[1][1], qf[1][2], qf[1][3], kb0[2], kb0[3]);
            mma_f16(c[nt], qf[2][0], qf[2][1], qf[2][2], qf[2][3], kb1[0], kb1[1]);
            mma_f16(c[nt], qf[3][0], qf[3][1], qf[3][2], qf[3][3], kb1[2], kb1[3]);
        }

        // ---- causal mask on diagonal tile --------------------------------
        if (kt == mt) {
            const int i0 = wid * 16 + (lane >> 2);
#pragma unroll
            for (int nt = 0; nt < 8; nt++) {
                const int j0 = nt * 8 + (lane & 3) * 2;
                if (j0     > i0)     c[nt][0] = -1e30f;
                if (j0 + 1 > i0)     c[nt][1] = -1e30f;
                if (j0     > i0 + 8) c[nt][2] = -1e30f;
                if (j0 + 1 > i0 + 8) c[nt][3] = -1e30f;
            }
        }

        // ---- online softmax ----------------------------------------------
        float t0 = -1e30f, t1 = -1e30f;
#pragma unroll
        for (int nt = 0; nt < 8; nt++) {
            t0 = fmaxf(t0, fmaxf(c[nt][0], c[nt][1]));
            t1 = fmaxf(t1, fmaxf(c[nt][2], c[nt][3]));
        }
        t0 = fmaxf(t0, __shfl_xor_sync(0xffffffffu, t0, 1));
        t0 = fmaxf(t0, __shfl_xor_sync(0xffffffffu, t0, 2));
        t1 = fmaxf(t1, __shfl_xor_sync(0xffffffffu, t1, 1));
        t1 = fmaxf(t1, __shfl_xor_sync(0xffffffffu, t1, 2));
        const float mn0 = fmaxf(m0r, t0);
        const float mn1 = fmaxf(m1r, t1);
        const float al0 = __expf(m0r - mn0);
        const float al1 = __expf(m1r - mn1);
        m0r = mn0; m1r = mn1;

        float s0 = 0.f, s1 = 0.f;
#pragma unroll
        for (int nt = 0; nt < 8; nt++) {
            c[nt][0] = __expf(c[nt][0] - mn0);
            c[nt][1] = __expf(c[nt][1] - mn0);
            c[nt][2] = __expf(c[nt][2] - mn1);
            c[nt][3] = __expf(c[nt][3] - mn1);
            s0 += c[nt][0] + c[nt][1];
            s1 += c[nt][2] + c[nt][3];
        }
        s0 += __shfl_xor_sync(0xffffffffu, s0, 1);
        s0 += __shfl_xor_sync(0xffffffffu, s0, 2);
        s1 += __shfl_xor_sync(0xffffffffu, s1, 1);
        s1 += __shfl_xor_sync(0xffffffffu, s1, 2);
        l0r = l0r * al0 + s0;
        l1r = l1r * al1 + s1;

#pragma unroll
        for (int nt = 0; nt < 8; nt++) {
            o[nt][0] *= al0; o[nt][1] *= al0;
            o[nt][2] *= al1; o[nt][3] *= al1;
        }

        // ---- O += P V (1 MMA per frag) -----------------------------------
#pragma unroll
        for (int kc = 0; kc < 4; kc++) {
            uint32_t ph[4];
            const float* p0 = c[2*kc];
            const float* p1 = c[2*kc+1];
            ph[0] = pack_h2(p0[0], p0[1]);
            ph[1] = pack_h2(p0[2], p0[3]);
            ph[2] = pack_h2(p1[0], p1[1]);
            ph[3] = pack_h2(p1[2], p1[3]);
#pragma unroll
            for (int ntp = 0; ntp < 4; ntp++) {
                const int row = kc * 16 + (grp & 1) * 8 + rr;
                const int ch  = ntp * 2 + (grp >> 1);
                uint32_t v0, v1, v2, v3;
                ldsm4t(v0, v1, v2, v3, st + 8192u + fsw(row, ch));
                mma_f16(o[2*ntp],   ph[0], ph[1], ph[2], ph[3], v0, v1);
                mma_f16(o[2*ntp+1], ph[0], ph[1], ph[2], ph[3], v2, v3);
            }
        }
        __syncthreads();     // all reads of this buffer done before refill
    }

    // ---- finalize + write plain fp16 [B,S,D] --------------------------------
    const float inv0 = 1.f / l0r;
    const float inv1 = 1.f / l1r;
    const int b = bh >> 4;
    const int h = bh & (H_ - 1);
    const int sq0 = mt * 64 + wid * 16 + (lane >> 2);
    const size_t base0 = ((size_t)(b * S_ + sq0)) * D_ + h * HD;
    const size_t base1 = base0 + (size_t)8 * D_;
#pragma unroll
    for (int nt = 0; nt < 8; nt++) {
        const int col = nt * 8 + (lane & 3) * 2;
        {
            __half2 hp = __floats2half2_rn(o[nt][0] * inv0, o[nt][1] * inv0);
            *(__half2*)(Oatt + base0 + col) = hp;
        }
        {
            __half2 hp = __floats2half2_rn(o[nt][2] * inv1, o[nt][3] * inv1);
            *(__half2*)(Oatt + base1 + col) = hp;
        }
    }
}

// ---------------- launch -----------------------------------------------------
extern "C" void kernel_launch(void* const* d_in, const int* in_sizes, int n_in,
                              void* d_out, int out_size)
{
    const float* x  = (const float*)d_in[0];
    float* out = (float*)d_out;

    void *pq, *pk, *pv, *pxh, *pwh, *patt, *prope;
    cudaGetSymbolAddress(&pq,  g_q);
    cudaGetSymbolAddress(&pk,  g_k);
    cudaGetSymbolAddress(&pv,  g_v);
    cudaGetSymbolAddress(&pxh, g_xh);
    cudaGetSymbolAddress(&pwh, g_wh);
    cudaGetSymbolAddress(&patt, g_att);
    cudaGetSymbolAddress(&prope, g_rope);

    cudaFuncSetAttribute(gemm_mma<1>, cudaFuncAttributeMaxDynamicSharedMemorySize, GSMEM);
    cudaFuncSetAttribute(gemm_mma<0>, cudaFuncAttributeMaxDynamicSharedMemorySize, GSMEM);
    cudaFuncSetAttribute(flash_mma, cudaFuncAttributeMaxDynamicSharedMemorySize, FSMEM);

    __half* xh = (__half*)pxh;
    __half* wh = (__half*)pwh;

    // RoPE table + fused fp32->fp16 converts
    rope_kernel<<<(S_ * 32 + 255) / 256, 256>>>((float2*)prope);
    split_all<<<(8 * RW) / 256, 256>>>(x, (const float*)d_in[1], (const float*)d_in[2],
                                       (const float*)d_in[3], (const float*)d_in[4],
                                       xh, wh);

    // fused QKV projection -> plain fp16 [B,H,S,hd]
    dim3 qkvgrid(3 * D_ / 128, MTOT / 128);   // (24, 32)
    gemm_mma<1><<<qkvgrid, 256, GSMEM>>>(xh, wh, nullptr,
        (__half*)pq, (__half*)pk, (__half*)pv);

    // tensor-core causal flash attention -> plain fp16 [B,S,D]
    dim3 agrid(S_ / 64, B_ * H_);        // (32, 32), 3 CTAs/SM
    flash_mma<<<agrid, 128, FSMEM>>>((const __half*)pq, (const __half*)pk,
                                     (const __half*)pv, (__half*)patt);

    // output projection -> d_out (fp32)
    dim3 ogrid(D_ / 128, MTOT / 128);    // (8, 32)
    gemm_mma<0><<<ogrid, 256, GSMEM>>>((const __half*)patt,
                                       wh + 3*(size_t)D_*D_,
                                       out, nullptr, nullptr, nullptr);
}

// round 13
// speedup vs baseline: 1.8029x; 1.1221x over previous
#include <cuda_runtime.h>
#include <cuda_fp16.h>
#include <cstdint>
#include <math.h>

// ---------------- problem shape ----------------------------------------------
#define B_   2
#define S_   2048
#define D_   1024
#define H_   16
#define HD   64
#define MTOT (B_*S_)          // 4096
// 1/sqrt(64) * log2(e): scores produced directly in log2 domain for exp2f
#define QSCALE (0.125f * 1.44269504088896f)

// ---------------- baseline-PTX helpers (compile at compute_103) --------------
__device__ __forceinline__ uint32_t smem_u32(const void* p) {
    uint32_t a;
    asm("{ .reg .u64 t; cvta.to.shared.u64 t, %1; cvt.u32.u64 %0, t; }"
        : "=r"(a) : "l"(p));
    return a;
}
#define CP_ASYNC16(dst, src) \
    asm volatile("cp.async.cg.shared.global [%0], [%1], 16;" :: "r"(dst), "l"(src))
#define CP_COMMIT() asm volatile("cp.async.commit_group;" ::: "memory")
#define CP_WAIT1()  asm volatile("cp.async.wait_group 1;" ::: "memory")
#define CP_WAIT0()  asm volatile("cp.async.wait_group 0;" ::: "memory")

__device__ __forceinline__ void ldsm4(uint32_t& r0, uint32_t& r1,
                                      uint32_t& r2, uint32_t& r3, uint32_t a) {
    asm volatile("ldmatrix.sync.aligned.m8n8.x4.shared.b16 {%0,%1,%2,%3}, [%4];"
                 : "=r"(r0), "=r"(r1), "=r"(r2), "=r"(r3) : "r"(a));
}
__device__ __forceinline__ void ldsm4t(uint32_t& r0, uint32_t& r1,
                                       uint32_t& r2, uint32_t& r3, uint32_t a) {
    asm volatile("ldmatrix.sync.aligned.m8n8.x4.trans.shared.b16 {%0,%1,%2,%3}, [%4];"
                 : "=r"(r0), "=r"(r1), "=r"(r2), "=r"(r3) : "r"(a));
}
__device__ __forceinline__ void mma_f16(float* c,
    uint32_t a0, uint32_t a1, uint32_t a2, uint32_t a3, uint32_t b0, uint32_t b1) {
    asm volatile("mma.sync.aligned.m16n8k16.row.col.f32.f16.f16.f32 "
                 "{%0,%1,%2,%3}, {%4,%5,%6,%7}, {%8,%9}, {%0,%1,%2,%3};"
                 : "+f"(c[0]), "+f"(c[1]), "+f"(c[2]), "+f"(c[3])
                 : "r"(a0), "r"(a1), "r"(a2), "r"(a3), "r"(b0), "r"(b1));
}
__device__ __forceinline__ uint32_t pack_h2(float a, float b) {
    __half2 t = __floats2half2_rn(a, b);
    return *(uint32_t*)&t;
}

// ---------------- scratch (device globals; no allocations allowed) ----------
__device__ __half g_q  [(size_t)B_*H_*S_*HD];
__device__ __half g_k  [(size_t)B_*H_*S_*HD];
__device__ __half g_v  [(size_t)B_*H_*S_*HD];
__device__ __half g_xh [(size_t)MTOT*D_];
__device__ __half g_wh [(size_t)4*D_*D_];                        // Wq|Wk|Wv|Wo
__device__ __half g_att[(size_t)MTOT*D_];
__device__ float2 g_rope[(size_t)S_*32];          // (cos,sin) per (spos, d/2)

// ---------------- RoPE table (exact sincosf, one-time) -----------------------
__global__ void rope_kernel(float2* __restrict__ t)
{
    int i = blockIdx.x * blockDim.x + threadIdx.x;    // over S_*32
    if (i >= S_ * 32) return;
    int spos = i >> 5, d2 = i & 31;
    float theta = powf(10000.0f, -2.0f * (float)d2 / (float)HD);
    float ang = (float)spos * theta;
    float ss, cc;
    sincosf(ang, &ss, &cc);
    t[i] = make_float2(cc, ss);
}

// ---------------- fused fp32 -> fp16 convert for x + 4 W ---------------------
#define RW  ((D_*D_)/4)        // 262144 float4 per weight
__global__ void split_all(const float* __restrict__ x,
                          const float* __restrict__ w0, const float* __restrict__ w1,
                          const float* __restrict__ w2, const float* __restrict__ w3,
                          __half* __restrict__ xh, __half* __restrict__ wh)
{
    int i = blockIdx.x * blockDim.x + threadIdx.x;    // float4 index, 8*RW total
    const float* src;
    __half* hi;
    int local;
    if (i < 4 * RW) {
        src = x; hi = xh; local = i;
    } else {
        int ip = i - 4 * RW;
        int r  = ip >> 18;     // RW = 2^18
        local  = ip & (RW - 1);
        src = (r == 0) ? w0 : (r == 1) ? w1 : (r == 2) ? w2 : w3;
        hi = wh + (size_t)r * D_ * D_;
    }
    float4 v = ((const float4*)src)[local];
    __half2 a = __floats2half2_rn(v.x, v.y);
    __half2 b = __floats2half2_rn(v.z, v.w);
    ((__half2*)hi)[2*local]   = a;
    ((__half2*)hi)[2*local+1] = b;
}

// ---------------- shared 128B-row swizzle ------------------------------------
__device__ __forceinline__ uint32_t fsw(int row, int c) {   // c in 0..7 (16B)
    return (uint32_t)(row * 128 + ((c ^ (row & 7)) << 4));
}

// ---------------- HMMA GEMM (2-stage, BK=64): C = A W^T ----------------------
// Plain fp16, 1 MMA per fragment. Stage = A(16K)|B(16K) = 32KB, 2 stages =
// 64KB -> 2 CTAs/SM; 32 barriers per CTA (BK=64 halves sync count).
#define BKG 64
#define NKI (D_/BKG)       // 16
#define STG 32768          // bytes per stage
#define GSMEM (2*STG)      // 64 KB

__device__ __forceinline__ void stage_load(
    uint32_t sb, int s, int k0, int tid, int m0, int n0,
    const __half* __restrict__ A, const __half* __restrict__ B)
{
    const uint32_t base = sb + (uint32_t)s * STG;
#pragma unroll
    for (int p = 0; p < 4; p++) {
        const int gi  = tid + p * 256;       // 0..1023
        const int row = gi >> 3;             // 0..127
        const int c   = gi & 7;
        const uint32_t so = fsw(row, c);
        CP_ASYNC16(base + 0     + so, A + (size_t)(m0 + row) * D_ + k0 + c * 8);
        CP_ASYNC16(base + 16384 + so, B + (size_t)(n0 + row) * D_ + k0 + c * 8);
    }
}

// QKV=1: n0 in [0,3072): B = Wq|Wk|Wv rows; RoPE/scale + fp16 scatter.
// QKV=0: n0 in [0,1024): B = Wo rows; fp32 [M,D] output.
template<int QKV>
__global__ __launch_bounds__(256, 2)
void gemm_mma(const __half* __restrict__ A, const __half* __restrict__ B,
              float* __restrict__ Cf,
              __half* __restrict__ Qp, __half* __restrict__ Kp,
              __half* __restrict__ Vp)
{
    extern __shared__ char smem[];
    const uint32_t sb = smem_u32(smem);
    const int tid  = threadIdx.x;
    const int wid  = tid >> 5;
    const int lane = tid & 31;
    const int m0 = blockIdx.y * 128;
    const int n0 = blockIdx.x * 128;
    const int wm = (wid & 1) * 64;
    const int wn = (wid >> 1) * 32;
    const int w  = QKV ? (n0 >> 10) : 3;

    float acc[4][4][4];
#pragma unroll
    for (int a = 0; a < 4; a++)
#pragma unroll
        for (int b = 0; b < 4; b++)
#pragma unroll
            for (int c = 0; c < 4; c++) acc[a][b][c] = 0.f;

    stage_load(sb, 0, 0, tid, m0, n0, A, B);
    CP_COMMIT();

    const int g = lane >> 3;
    const int r = lane & 7;

    for (int i = 0; i < NKI; i++) {
        if (i + 1 < NKI) {
            stage_load(sb, (i + 1) & 1, (i + 1) * BKG, tid, m0, n0, A, B);
            CP_COMMIT();
            CP_WAIT1();
        } else {
            CP_WAIT0();
        }
        __syncthreads();     // cross-thread visibility of stage i's cp.asyncs
        const uint32_t base = sb + (uint32_t)(i & 1) * STG;
#pragma unroll
        for (int h = 0; h < 4; h++) {
            uint32_t ah[4][4], bhf[2][4];
#pragma unroll
            for (int mi = 0; mi < 4; mi++) {
                const int arow = wm + mi * 16 + (g & 1) * 8 + r;
                const int akc  = h * 2 + (g >> 1);
                ldsm4(ah[mi][0], ah[mi][1], ah[mi][2], ah[mi][3],
                      base + 0 + fsw(arow, akc));
            }
#pragma unroll
            for (int ng = 0; ng < 2; ng++) {
                const int brow = wn + ng * 16 + (g >> 1) * 8 + r;
                const int bkc  = h * 2 + (g & 1);
                ldsm4(bhf[ng][0], bhf[ng][1], bhf[ng][2], bhf[ng][3],
                      base + 16384 + fsw(brow, bkc));
            }
#pragma unroll
            for (int mi = 0; mi < 4; mi++)
#pragma unroll
                for (int ni = 0; ni < 4; ni++) {
                    const uint32_t* bh = &bhf[ni >> 1][(ni & 1) * 2];
                    mma_f16(acc[mi][ni], ah[mi][0], ah[mi][1], ah[mi][2], ah[mi][3], bh[0], bh[1]);
                }
        }
        __syncthreads();     // all reads of this stage done before refill
    }

    // ---------------- epilogue ------------------------------------------------
    const int tg = lane >> 2;
    const int tq = lane & 3;
#pragma unroll
    for (int mi = 0; mi < 4; mi++) {
#pragma unroll
        for (int hf = 0; hf < 2; hf++) {
            const int m    = m0 + wm + mi * 16 + hf * 8 + tg;
            const int spos = m & (S_ - 1);
            const int bb   = m >> 11;
#pragma unroll
            for (int ni = 0; ni < 4; ni++) {
                const int n = n0 + wn + ni * 8 + tq * 2;     // even (global)
                float v1 = acc[mi][ni][hf * 2 + 0];
                float v2 = acc[mi][ni][hf * 2 + 1];
                if (QKV) {
                    const int nl = n & 1023;
                    const int d  = nl & (HD - 1);
                    if (w < 2) {
                        float2 cs = g_rope[spos * 32 + (d >> 1)];
                        float y1 = v1 * cs.x - v2 * cs.y;
                        float y2 = v1 * cs.y + v2 * cs.x;
                        v1 = y1; v2 = y2;
                    }
                    if (w == 0) { v1 *= QSCALE; v2 *= QSCALE; }   // scores in log2 domain
                    const int hh = nl >> 6;
                    const size_t idx = (((size_t)(bb * H_ + hh) * S_) + spos) * HD + d;
                    __half2 hp = __floats2half2_rn(v1, v2);
                    __half* C = (w == 0) ? Qp : (w == 1) ? Kp : Vp;
                    *(__half2*)(C + idx) = hp;
                } else {
                    float* p = Cf + (size_t)m * D_ + n;
                    *(float2*)p = make_float2(v1, v2);
                }
            }
        }
    }
}

// ---------------- HMMA flash attention (causal), plain fp16 ------------------
// 128 threads (4 warps), Q tile 64 rows, K/V tiles 64 rows, double-buffered.
// Scores arrive in log2 domain (Q pre-scaled) -> softmax uses raw exp2f.
// Stage = K(8K)|V(8K) = 16KB; Q staged through stage-0; smem 32KB; 2 CTAs/SM.
#define FSTG    16384u
#define FSMEM   (2*16384)

__device__ __forceinline__ void fa_stage(
    uint32_t base, const __half* k, const __half* v, int s0, int tid)
{
#pragma unroll
    for (int p = 0; p < 4; p++) {
        const int gi  = tid + p * 128;       // 0..511
        const int row = gi >> 3;
        const int c   = gi & 7;
        const uint32_t off = fsw(row, c);
        const size_t g = (size_t)(s0 + row) * HD + c * 8;
        CP_ASYNC16(base + 0u    + off, k + g);
        CP_ASYNC16(base + 8192u + off, v + g);
    }
}

__global__ __launch_bounds__(128, 2)
void flash_mma(const __half* __restrict__ Q, const __half* __restrict__ K,
               const __half* __restrict__ V, __half* __restrict__ Oatt)
{
    extern __shared__ char smem[];
    const uint32_t sb = smem_u32(smem);
    const int tid  = threadIdx.x;
    const int wid  = tid >> 5;
    const int lane = tid & 31;
    const int bh = blockIdx.y;
    const int mt = (int)gridDim.x - 1 - (int)blockIdx.x;   // big tiles first
    const int nkt = mt + 1;                                // 64-row K tiles

    const __half* qb_ = Q + ((size_t)bh * S_) * HD;
    const __half* kb_ = K + ((size_t)bh * S_) * HD;
    const __half* vb_ = V + ((size_t)bh * S_) * HD;

    const int grp = lane >> 3;
    const int rr  = lane & 7;

    // ---- stage Q (plain) through stage-0 buffer, extract frags -------------
#pragma unroll
    for (int p = 0; p < 4; p++) {
        const int gi  = tid + p * 128;       // 0..511
        const int row = gi >> 3;
        const int c   = gi & 7;
        CP_ASYNC16(sb + fsw(row, c), qb_ + (size_t)(mt * 64 + row) * HD + c * 8);
    }
    CP_COMMIT();
    CP_WAIT0();
    __syncthreads();

    uint32_t qf[4][4];
#pragma unroll
    for (int kc = 0; kc < 4; kc++) {
        const int row = wid * 16 + (grp & 1) * 8 + rr;
        const int c   = kc * 2 + (grp >> 1);
        ldsm4(qf[kc][0], qf[kc][1], qf[kc][2], qf[kc][3], sb + fsw(row, c));
    }
    __syncthreads();     // Q frags extracted before stage-0 is overwritten

    fa_stage(sb, kb_, vb_, 0, tid);
    CP_COMMIT();

    float o[8][4];
#pragma unroll
    for (int a = 0; a < 8; a++)
#pragma unroll
        for (int b = 0; b < 4; b++) o[a][b] = 0.f;
    float m0r = -1e30f, m1r = -1e30f, l0r = 0.f, l1r = 0.f;

    for (int kt = 0; kt < nkt; kt++) {
        if (kt + 1 < nkt) {
            fa_stage(sb + (uint32_t)((kt + 1) & 1) * FSTG,
                     kb_, vb_, (kt + 1) * 64, tid);
            CP_COMMIT();
            CP_WAIT1();
        } else {
            CP_WAIT0();
        }
        __syncthreads();     // stage kt visible to all threads

        const uint32_t st = sb + (uint32_t)(kt & 1) * FSTG;

        // ---- scores S = Q K^T (log2 domain) : 1 MMA per kc ---------------
        float c[8][4];
#pragma unroll
        for (int a = 0; a < 8; a++)
#pragma unroll
            for (int b = 0; b < 4; b++) c[a][b] = 0.f;

#pragma unroll
        for (int nt = 0; nt < 8; nt++) {
            const int j = nt * 8 + rr;
            uint32_t kb0[4], kb1[4];
            ldsm4(kb0[0], kb0[1], kb0[2], kb0[3], st + fsw(j, 0 + grp));
            ldsm4(kb1[0], kb1[1], kb1[2], kb1[3], st + fsw(j, 4 + grp));
            mma_f16(c[nt], qf[0][0], qf[0][1], qf[0][2], qf[0][3], kb0[0], kb0[1]);
            mma_f16(c[nt], qf[1][0], qf[1][1], qf[1][2], qf[1][3], kb0[2], kb0[3]);
            mma_f16(c[nt], qf[2][0], qf[2][1], qf[2][2], qf[2][3], kb1[0], kb1[1]);
            mma_f16(c[nt], qf[3][0], qf[3][1], qf[3][2], qf[3][3], kb1[2], kb1[3]);
        }

        // ---- causal mask on diagonal tile --------------------------------
        if (kt == mt) {
            const int i0 = wid * 16 + (lane >> 2);
#pragma unroll
            for (int nt = 0; nt < 8; nt++) {
                const int j0 = nt * 8 + (lane & 3) * 2;
                if (j0     > i0)     c[nt][0] = -1e30f;
                if (j0 + 1 > i0)     c[nt][1] = -1e30f;
                if (j0     > i0 + 8) c[nt][2] = -1e30f;
                if (j0 + 1 > i0 + 8) c[nt][3] = -1e30f;
            }
        }

        // ---- online softmax (exp2 domain) --------------------------------
        float t0 = -1e30f, t1 = -1e30f;
#pragma unroll
        for (int nt = 0; nt < 8; nt++) {
            t0 = fmaxf(t0, fmaxf(c[nt][0], c[nt][1]));
            t1 = fmaxf(t1, fmaxf(c[nt][2], c[nt][3]));
        }
        t0 = fmaxf(t0, __shfl_xor_sync(0xffffffffu, t0, 1));
        t0 = fmaxf(t0, __shfl_xor_sync(0xffffffffu, t0, 2));
        t1 = fmaxf(t1, __shfl_xor_sync(0xffffffffu, t1, 1));
        t1 = fmaxf(t1, __shfl_xor_sync(0xffffffffu, t1, 2));
        const float mn0 = fmaxf(m0r, t0);
        const float mn1 = fmaxf(m1r, t1);
        const float al0 = exp2f(m0r - mn0);
        const float al1 = exp2f(m1r - mn1);
        m0r = mn0; m1r = mn1;

        float s0 = 0.f, s1 = 0.f;
#pragma unroll
        for (int nt = 0; nt < 8; nt++) {
            c[nt][0] = exp2f(c[nt][0] - mn0);
            c[nt][1] = exp2f(c[nt][1] - mn0);
            c[nt][2] = exp2f(c[nt][2] - mn1);
            c[nt][3] = exp2f(c[nt][3] - mn1);
            s0 += c[nt][0] + c[nt][1];
            s1 += c[nt][2] + c[nt][3];
        }
        s0 += __shfl_xor_sync(0xffffffffu, s0, 1);
        s0 += __shfl_xor_sync(0xffffffffu, s0, 2);
        s1 += __shfl_xor_sync(0xffffffffu, s1, 1);
        s1 += __shfl_xor_sync(0xffffffffu, s1, 2);
        l0r = l0r * al0 + s0;
        l1r = l1r * al1 + s1;

#pragma unroll
        for (int nt = 0; nt < 8; nt++) {
            o[nt][0] *= al0; o[nt][1] *= al0;
            o[nt][2] *= al1; o[nt][3] *= al1;
        }

        // ---- O += P V (1 MMA per frag) -----------------------------------
#pragma unroll
        for (int kc = 0; kc < 4; kc++) {
            uint32_t ph[4];
            const float* p0 = c[2*kc];
            const float* p1 = c[2*kc+1];
            ph[0] = pack_h2(p0[0], p0[1]);
            ph[1] = pack_h2(p0[2], p0[3]);
            ph[2] = pack_h2(p1[0], p1[1]);
            ph[3] = pack_h2(p1[2], p1[3]);
#pragma unroll
            for (int ntp = 0; ntp < 4; ntp++) {
                const int row = kc * 16 + (grp & 1) * 8 + rr;
                const int ch  = ntp * 2 + (grp >> 1);
                uint32_t v0, v1, v2, v3;
                ldsm4t(v0, v1, v2, v3, st + 8192u + fsw(row, ch));
                mma_f16(o[2*ntp],   ph[0], ph[1], ph[2], ph[3], v0, v1);
                mma_f16(o[2*ntp+1], ph[0], ph[1], ph[2], ph[3], v2, v3);
            }
        }
        __syncthreads();     // all reads of this buffer done before refill
    }

    // ---- finalize + write plain fp16 [B,S,D] --------------------------------
    const float inv0 = 1.f / l0r;
    const float inv1 = 1.f / l1r;
    const int b = bh >> 4;
    const int h = bh & (H_ - 1);
    const int sq0 = mt * 64 + wid * 16 + (lane >> 2);
    const size_t base0 = ((size_t)(b * S_ + sq0)) * D_ + h * HD;
    const size_t base1 = base0 + (size_t)8 * D_;
#pragma unroll
    for (int nt = 0; nt < 8; nt++) {
        const int col = nt * 8 + (lane & 3) * 2;
        {
            __half2 hp = __floats2half2_rn(o[nt][0] * inv0, o[nt][1] * inv0);
            *(__half2*)(Oatt + base0 + col) = hp;
        }
        {
            __half2 hp = __floats2half2_rn(o[nt][2] * inv1, o[nt][3] * inv1);
            *(__half2*)(Oatt + base1 + col) = hp;
        }
    }
}

// ---------------- launch -----------------------------------------------------
extern "C" void kernel_launch(void* const* d_in, const int* in_sizes, int n_in,
                              void* d_out, int out_size)
{
    const float* x  = (const float*)d_in[0];
    float* out = (float*)d_out;

    void *pq, *pk, *pv, *pxh, *pwh, *patt, *prope;
    cudaGetSymbolAddress(&pq,  g_q);
    cudaGetSymbolAddress(&pk,  g_k);
    cudaGetSymbolAddress(&pv,  g_v);
    cudaGetSymbolAddress(&pxh, g_xh);
    cudaGetSymbolAddress(&pwh, g_wh);
    cudaGetSymbolAddress(&patt, g_att);
    cudaGetSymbolAddress(&prope, g_rope);

    cudaFuncSetAttribute(gemm_mma<1>, cudaFuncAttributeMaxDynamicSharedMemorySize, GSMEM);
    cudaFuncSetAttribute(gemm_mma<0>, cudaFuncAttributeMaxDynamicSharedMemorySize, GSMEM);
    cudaFuncSetAttribute(flash_mma, cudaFuncAttributeMaxDynamicSharedMemorySize, FSMEM);

    __half* xh = (__half*)pxh;
    __half* wh = (__half*)pwh;

    // RoPE table + fused fp32->fp16 converts
    rope_kernel<<<(S_ * 32 + 255) / 256, 256>>>((float2*)prope);
    split_all<<<(8 * RW) / 256, 256>>>(x, (const float*)d_in[1], (const float*)d_in[2],
                                       (const float*)d_in[3], (const float*)d_in[4],
                                       xh, wh);

    // fused QKV projection -> plain fp16 [B,H,S,hd]
    dim3 qkvgrid(3 * D_ / 128, MTOT / 128);   // (24, 32)
    gemm_mma<1><<<qkvgrid, 256, GSMEM>>>(xh, wh, nullptr,
        (__half*)pq, (__half*)pk, (__half*)pv);

    // tensor-core causal flash attention -> plain fp16 [B,S,D]
    dim3 agrid(S_ / 64, B_ * H_);        // (32, 32), 2 CTAs/SM
    flash_mma<<<agrid, 128, FSMEM>>>((const __half*)pq, (const __half*)pk,
                                     (const __half*)pv, (__half*)patt);

    // output projection -> d_out (fp32)
    dim3 ogrid(D_ / 128, MTOT / 128);    // (8, 32)
    gemm_mma<0><<<ogrid, 256, GSMEM>>>((const __half*)patt,
                                       wh + 3*(size_t)D_*D_,
                                       out, nullptr, nullptr, nullptr);
}

// round 14
// speedup vs baseline: 2.7878x; 1.5462x over previous
#include <cuda_runtime.h>
#include <cuda_fp16.h>
#include <cstdint>
#include <math.h>

// ---------------- problem shape ----------------------------------------------
#define B_   2
#define S_   2048
#define D_   1024
#define H_   16
#define HD   64
#define MTOT (B_*S_)          // 4096
// 1/sqrt(64) * log2(e): scores produced directly in log2 domain for exp2f
#define QSCALE (0.125f * 1.44269504088896f)

// ---------------- baseline-PTX helpers (compile at compute_103) --------------
__device__ __forceinline__ uint32_t smem_u32(const void* p) {
    uint32_t a;
    asm("{ .reg .u64 t; cvta.to.shared.u64 t, %1; cvt.u32.u64 %0, t; }"
        : "=r"(a) : "l"(p));
    return a;
}
#define CP_ASYNC16(dst, src) \
    asm volatile("cp.async.cg.shared.global [%0], [%1], 16;" :: "r"(dst), "l"(src))
#define CP_COMMIT() asm volatile("cp.async.commit_group;" ::: "memory")
#define CP_WAIT1()  asm volatile("cp.async.wait_group 1;" ::: "memory")
#define CP_WAIT0()  asm volatile("cp.async.wait_group 0;" ::: "memory")

__device__ __forceinline__ void ldsm4(uint32_t& r0, uint32_t& r1,
                                      uint32_t& r2, uint32_t& r3, uint32_t a) {
    asm volatile("ldmatrix.sync.aligned.m8n8.x4.shared.b16 {%0,%1,%2,%3}, [%4];"
                 : "=r"(r0), "=r"(r1), "=r"(r2), "=r"(r3) : "r"(a));
}
__device__ __forceinline__ void ldsm4t(uint32_t& r0, uint32_t& r1,
                                       uint32_t& r2, uint32_t& r3, uint32_t a) {
    asm volatile("ldmatrix.sync.aligned.m8n8.x4.trans.shared.b16 {%0,%1,%2,%3}, [%4];"
                 : "=r"(r0), "=r"(r1), "=r"(r2), "=r"(r3) : "r"(a));
}
__device__ __forceinline__ void mma_f16(float* c,
    uint32_t a0, uint32_t a1, uint32_t a2, uint32_t a3, uint32_t b0, uint32_t b1) {
    asm volatile("mma.sync.aligned.m16n8k16.row.col.f32.f16.f16.f32 "
                 "{%0,%1,%2,%3}, {%4,%5,%6,%7}, {%8,%9}, {%0,%1,%2,%3};"
                 : "+f"(c[0]), "+f"(c[1]), "+f"(c[2]), "+f"(c[3])
                 : "r"(a0), "r"(a1), "r"(a2), "r"(a3), "r"(b0), "r"(b1));
}
__device__ __forceinline__ uint32_t pack_h2(float a, float b) {
    __half2 t = __floats2half2_rn(a, b);
    return *(uint32_t*)&t;
}

// ---------------- scratch (device globals; no allocations allowed) ----------
__device__ __half g_q  [(size_t)B_*H_*S_*HD];
__device__ __half g_k  [(size_t)B_*H_*S_*HD];
__device__ __half g_v  [(size_t)B_*H_*S_*HD];
__device__ __half g_xh [(size_t)MTOT*D_];
__device__ __half g_wh [(size_t)4*D_*D_];                        // Wq|Wk|Wv|Wo
__device__ __half g_att[(size_t)MTOT*D_];
__device__ float2 g_rope[(size_t)S_*32];          // (cos,sin) per (spos, d/2)

// ---------------- fused fp32->fp16 convert (x + 4 W) + RoPE table ------------
#define RW  ((D_*D_)/4)        // 262144 float4 per weight
#define NCVT (8*RW)            // convert work items
#define NROPE (S_*32)          // rope work items
__global__ void split_all(const float* __restrict__ x,
                          const float* __restrict__ w0, const float* __restrict__ w1,
                          const float* __restrict__ w2, const float* __restrict__ w3,
                          __half* __restrict__ xh, __half* __restrict__ wh,
                          float2* __restrict__ ropet)
{
    int i = blockIdx.x * blockDim.x + threadIdx.x;
    if (i >= NCVT) {
        int j = i - NCVT;
        if (j < NROPE) {
            int spos = j >> 5, d2 = j & 31;
            float theta = powf(10000.0f, -2.0f * (float)d2 / (float)HD);
            float ang = (float)spos * theta;
            float ss, cc;
            sincosf(ang, &ss, &cc);
            ropet[j] = make_float2(cc, ss);
        }
        return;
    }
    const float* src;
    __half* hi;
    int local;
    if (i < 4 * RW) {
        src = x; hi = xh; local = i;
    } else {
        int ip = i - 4 * RW;
        int r  = ip >> 18;     // RW = 2^18
        local  = ip & (RW - 1);
        src = (r == 0) ? w0 : (r == 1) ? w1 : (r == 2) ? w2 : w3;
        hi = wh + (size_t)r * D_ * D_;
    }
    float4 v = ((const float4*)src)[local];
    __half2 a = __floats2half2_rn(v.x, v.y);
    __half2 b = __floats2half2_rn(v.z, v.w);
    ((__half2*)hi)[2*local]   = a;
    ((__half2*)hi)[2*local+1] = b;
}

// ---------------- shared 128B-row swizzle ------------------------------------
__device__ __forceinline__ uint32_t fsw(int row, int c) {   // c in 0..7 (16B)
    return (uint32_t)(row * 128 + ((c ^ (row & 7)) << 4));
}

// ---------------- HMMA GEMM (2-stage, BK=64): C = A W^T ----------------------
#define BKG 64
#define NKI (D_/BKG)       // 16
#define STG 32768          // bytes per stage
#define GSMEM (2*STG)      // 64 KB

__device__ __forceinline__ void stage_load(
    uint32_t sb, int s, int k0, int tid, int m0, int n0,
    const __half* __restrict__ A, const __half* __restrict__ B)
{
    const uint32_t base = sb + (uint32_t)s * STG;
#pragma unroll
    for (int p = 0; p < 4; p++) {
        const int gi  = tid + p * 256;       // 0..1023
        const int row = gi >> 3;             // 0..127
        const int c   = gi & 7;
        const uint32_t so = fsw(row, c);
        CP_ASYNC16(base + 0     + so, A + (size_t)(m0 + row) * D_ + k0 + c * 8);
        CP_ASYNC16(base + 16384 + so, B + (size_t)(n0 + row) * D_ + k0 + c * 8);
    }
}

// QKV=1: n0 in [0,3072): B = Wq|Wk|Wv rows; RoPE/scale + fp16 scatter.
// QKV=0: n0 in [0,1024): B = Wo rows; fp32 [M,D] output.
template<int QKV>
__global__ __launch_bounds__(256, 2)
void gemm_mma(const __half* __restrict__ A, const __half* __restrict__ B,
              float* __restrict__ Cf,
              __half* __restrict__ Qp, __half* __restrict__ Kp,
              __half* __restrict__ Vp)
{
    extern __shared__ char smem[];
    const uint32_t sb = smem_u32(smem);
    const int tid  = threadIdx.x;
    const int wid  = tid >> 5;
    const int lane = tid & 31;
    const int m0 = blockIdx.y * 128;
    const int n0 = blockIdx.x * 128;
    const int wm = (wid & 1) * 64;
    const int wn = (wid >> 1) * 32;
    const int w  = QKV ? (n0 >> 10) : 3;

    float acc[4][4][4];
#pragma unroll
    for (int a = 0; a < 4; a++)
#pragma unroll
        for (int b = 0; b < 4; b++)
#pragma unroll
            for (int c = 0; c < 4; c++) acc[a][b][c] = 0.f;

    stage_load(sb, 0, 0, tid, m0, n0, A, B);
    CP_COMMIT();

    const int g = lane >> 3;
    const int r = lane & 7;

    for (int i = 0; i < NKI; i++) {
        if (i + 1 < NKI) {
            stage_load(sb, (i + 1) & 1, (i + 1) * BKG, tid, m0, n0, A, B);
            CP_COMMIT();
            CP_WAIT1();
        } else {
            CP_WAIT0();
        }
        __syncthreads();     // cross-thread visibility of stage i's cp.asyncs
        const uint32_t base = sb + (uint32_t)(i & 1) * STG;
#pragma unroll
        for (int h = 0; h < 4; h++) {
            uint32_t ah[4][4], bhf[2][4];
#pragma unroll
            for (int mi = 0; mi < 4; mi++) {
                const int arow = wm + mi * 16 + (g & 1) * 8 + r;
                const int akc  = h * 2 + (g >> 1);
                ldsm4(ah[mi][0], ah[mi][1], ah[mi][2], ah[mi][3],
                      base + 0 + fsw(arow, akc));
            }
#pragma unroll
            for (int ng = 0; ng < 2; ng++) {
                const int brow = wn + ng * 16 + (g >> 1) * 8 + r;
                const int bkc  = h * 2 + (g & 1);
                ldsm4(bhf[ng][0], bhf[ng][1], bhf[ng][2], bhf[ng][3],
                      base + 16384 + fsw(brow, bkc));
            }
#pragma unroll
            for (int mi = 0; mi < 4; mi++)
#pragma unroll
                for (int ni = 0; ni < 4; ni++) {
                    const uint32_t* bh = &bhf[ni >> 1][(ni & 1) * 2];
                    mma_f16(acc[mi][ni], ah[mi][0], ah[mi][1], ah[mi][2], ah[mi][3], bh[0], bh[1]);
                }
        }
        __syncthreads();     // all reads of this stage done before refill
    }

    // ---------------- epilogue ------------------------------------------------
    const int tg = lane >> 2;
    const int tq = lane & 3;
#pragma unroll
    for (int mi = 0; mi < 4; mi++) {
#pragma unroll
        for (int hf = 0; hf < 2; hf++) {
            const int m    = m0 + wm + mi * 16 + hf * 8 + tg;
            const int spos = m & (S_ - 1);
            const int bb   = m >> 11;
#pragma unroll
            for (int ni = 0; ni < 4; ni++) {
                const int n = n0 + wn + ni * 8 + tq * 2;     // even (global)
                float v1 = acc[mi][ni][hf * 2 + 0];
                float v2 = acc[mi][ni][hf * 2 + 1];
                if (QKV) {
                    const int nl = n & 1023;
                    const int d  = nl & (HD - 1);
                    if (w < 2) {
                        float2 cs = g_rope[spos * 32 + (d >> 1)];
                        float y1 = v1 * cs.x - v2 * cs.y;
                        float y2 = v1 * cs.y + v2 * cs.x;
                        v1 = y1; v2 = y2;
                    }
                    if (w == 0) { v1 *= QSCALE; v2 *= QSCALE; }  // log2 domain
                    const int hh = nl >> 6;
                    const size_t idx = (((size_t)(bb * H_ + hh) * S_) + spos) * HD + d;
                    __half2 hp = __floats2half2_rn(v1, v2);
                    __half* C = (w == 0) ? Qp : (w == 1) ? Kp : Vp;
                    *(__half2*)(C + idx) = hp;
                } else {
                    float* p = Cf + (size_t)m * D_ + n;
                    *(float2*)p = make_float2(v1, v2);
                }
            }
        }
    }
}

// ---------------- HMMA flash attention (causal), plain fp16 ------------------
// 128 threads (4 warps), Q tile 64 rows, K/V tiles of 128 rows (halves per-
// tile softmax fixed costs + barriers per unit work), double-buffered.
// Stage = K(16K)|V(16K) = 32KB; smem 64KB; 2 CTAs/SM.
#define FSTG    32768u
#define FSMEM   (2*32768)

__device__ __forceinline__ void fa_stage(
    uint32_t base, const __half* k, const __half* v, int s0, int tid)
{
#pragma unroll
    for (int p = 0; p < 8; p++) {
        const int gi  = tid + p * 128;       // 0..1023
        const int row = gi >> 3;             // 0..127
        const int c   = gi & 7;
        const uint32_t off = fsw(row, c);
        const size_t g = (size_t)(s0 + row) * HD + c * 8;
        CP_ASYNC16(base + 0u     + off, k + g);
        CP_ASYNC16(base + 16384u + off, v + g);
    }
}

__global__ __launch_bounds__(128, 2)
void flash_mma(const __half* __restrict__ Q, const __half* __restrict__ K,
               const __half* __restrict__ V, __half* __restrict__ Oatt)
{
    extern __shared__ char smem[];
    const uint32_t sb = smem_u32(smem);
    const int tid  = threadIdx.x;
    const int wid  = tid >> 5;
    const int lane = tid & 31;
    const int bh = blockIdx.y;
    const int mt = (int)gridDim.x - 1 - (int)blockIdx.x;   // big tiles first
    const int nkt = (mt + 2) >> 1;        // 128-row K tiles covering (mt+1)*64

    const __half* qb_ = Q + ((size_t)bh * S_) * HD;
    const __half* kb_ = K + ((size_t)bh * S_) * HD;
    const __half* vb_ = V + ((size_t)bh * S_) * HD;

    const int grp = lane >> 3;
    const int rr  = lane & 7;

    // ---- stage Q (plain) through stage-0 buffer, extract frags -------------
#pragma unroll
    for (int p = 0; p < 4; p++) {
        const int gi  = tid + p * 128;       // 0..511
        const int row = gi >> 3;
        const int c   = gi & 7;
        CP_ASYNC16(sb + fsw(row, c), qb_ + (size_t)(mt * 64 + row) * HD + c * 8);
    }
    CP_COMMIT();
    CP_WAIT0();
    __syncthreads();

    uint32_t qf[4][4];
#pragma unroll
    for (int kc = 0; kc < 4; kc++) {
        const int row = wid * 16 + (grp & 1) * 8 + rr;
        const int c   = kc * 2 + (grp >> 1);
        ldsm4(qf[kc][0], qf[kc][1], qf[kc][2], qf[kc][3], sb + fsw(row, c));
    }
    __syncthreads();     // Q frags extracted before stage-0 is overwritten

    fa_stage(sb, kb_, vb_, 0, tid);
    CP_COMMIT();

    float o[8][4];
#pragma unroll
    for (int a = 0; a < 8; a++)
#pragma unroll
        for (int b = 0; b < 4; b++) o[a][b] = 0.f;
    float m0r = -1e30f, m1r = -1e30f, l0r = 0.f, l1r = 0.f;

    for (int kt = 0; kt < nkt; kt++) {
        if (kt + 1 < nkt) {
            fa_stage(sb + (uint32_t)((kt + 1) & 1) * FSTG,
                     kb_, vb_, (kt + 1) * 128, tid);
            CP_COMMIT();
            CP_WAIT1();
        } else {
            CP_WAIT0();
        }
        __syncthreads();     // stage kt visible to all threads

        const uint32_t st = sb + (uint32_t)(kt & 1) * FSTG;

        // ---- scores S = Q K^T over 128 columns (log2 domain) -------------
        float c[16][4];
#pragma unroll
        for (int a = 0; a < 16; a++)
#pragma unroll
            for (int b = 0; b < 4; b++) c[a][b] = 0.f;

#pragma unroll
        for (int nt = 0; nt < 16; nt++) {
            const int j = nt * 8 + rr;       // K row 0..127
            uint32_t kb0[4], kb1[4];
            ldsm4(kb0[0], kb0[1], kb0[2], kb0[3], st + fsw(j, 0 + grp));
            ldsm4(kb1[0], kb1[1], kb1[2], kb1[3], st + fsw(j, 4 + grp));
            mma_f16(c[nt], qf[0][0], qf[0][1], qf[0][2], qf[0][3], kb0[0], kb0[1]);
            mma_f16(c[nt], qf[1][0], qf[1][1], qf[1][2], qf[1][3], kb0[2], kb0[3]);
            mma_f16(c[nt], qf[2][0], qf[2][1], qf[2][2], qf[2][3], kb1[0], kb1[1]);
            mma_f16(c[nt], qf[3][0], qf[3][1], qf[3][2], qf[3][3], kb1[2], kb1[3]);
        }

        // ---- causal mask on last tile (global coords) --------------------
        if (kt == nkt - 1) {
            const int ig = mt * 64 + wid * 16 + (lane >> 2);
#pragma unroll
            for (int nt = 0; nt < 16; nt++) {
                const int jg = kt * 128 + nt * 8 + (lane & 3) * 2;
                if (jg     > ig)     c[nt][0] = -1e30f;
                if (jg + 1 > ig)     c[nt][1] = -1e30f;
                if (jg     > ig + 8) c[nt][2] = -1e30f;
                if (jg + 1 > ig + 8) c[nt][3] = -1e30f;
            }
        }

        // ---- online softmax (exp2 domain) --------------------------------
        float t0 = -1e30f, t1 = -1e30f;
#pragma unroll
        for (int nt = 0; nt < 16; nt++) {
            t0 = fmaxf(t0, fmaxf(c[nt][0], c[nt][1]));
            t1 = fmaxf(t1, fmaxf(c[nt][2], c[nt][3]));
        }
        t0 = fmaxf(t0, __shfl_xor_sync(0xffffffffu, t0, 1));
        t0 = fmaxf(t0, __shfl_xor_sync(0xffffffffu, t0, 2));
        t1 = fmaxf(t1, __shfl_xor_sync(0xffffffffu, t1, 1));
        t1 = fmaxf(t1, __shfl_xor_sync(0xffffffffu, t1, 2));
        const float mn0 = fmaxf(m0r, t0);
        const float mn1 = fmaxf(m1r, t1);
        const float al0 = exp2f(m0r - mn0);
        const float al1 = exp2f(m1r - mn1);
        m0r = mn0; m1r = mn1;

        float s0 = 0.f, s1 = 0.f;
#pragma unroll
        for (int nt = 0; nt < 16; nt++) {
            c[nt][0] = exp2f(c[nt][0] - mn0);
            c[nt][1] = exp2f(c[nt][1] - mn0);
            c[nt][2] = exp2f(c[nt][2] - mn1);
            c[nt][3] = exp2f(c[nt][3] - mn1);
            s0 += c[nt][0] + c[nt][1];
            s1 += c[nt][2] + c[nt][3];
        }
        s0 += __shfl_xor_sync(0xffffffffu, s0, 1);
        s0 += __shfl_xor_sync(0xffffffffu, s0, 2);
        s1 += __shfl_xor_sync(0xffffffffu, s1, 1);
        s1 += __shfl_xor_sync(0xffffffffu, s1, 2);
        l0r = l0r * al0 + s0;
        l1r = l1r * al1 + s1;

#pragma unroll
        for (int nt = 0; nt < 8; nt++) {
            o[nt][0] *= al0; o[nt][1] *= al0;
            o[nt][2] *= al1; o[nt][3] *= al1;
        }

        // ---- O += P V (1 MMA per frag; kc 0..7 over 128 K rows) ----------
#pragma unroll
        for (int kc = 0; kc < 8; kc++) {
            uint32_t ph[4];
            const float* p0 = c[2*kc];
            const float* p1 = c[2*kc+1];
            ph[0] = pack_h2(p0[0], p0[1]);
            ph[1] = pack_h2(p0[2], p0[3]);
            ph[2] = pack_h2(p1[0], p1[1]);
            ph[3] = pack_h2(p1[2], p1[3]);
#pragma unroll
            for (int ntp = 0; ntp < 4; ntp++) {
                const int row = kc * 16 + (grp & 1) * 8 + rr;   // V row 0..127
                const int ch  = ntp * 2 + (grp >> 1);
                uint32_t v0, v1, v2, v3;
                ldsm4t(v0, v1, v2, v3, st + 16384u + fsw(row, ch));
                mma_f16(o[2*ntp],   ph[0], ph[1], ph[2], ph[3], v0, v1);
                mma_f16(o[2*ntp+1], ph[0], ph[1], ph[2], ph[3], v2, v3);
            }
        }
        __syncthreads();     // all reads of this buffer done before refill
    }

    // ---- finalize + write plain fp16 [B,S,D] --------------------------------
    const float inv0 = 1.f / l0r;
    const float inv1 = 1.f / l1r;
    const int b = bh >> 4;
    const int h = bh & (H_ - 1);
    const int sq0 = mt * 64 + wid * 16 + (lane >> 2);
    const size_t base0 = ((size_t)(b * S_ + sq0)) * D_ + h * HD;
    const size_t base1 = base0 + (size_t)8 * D_;
#pragma unroll
    for (int nt = 0; nt < 8; nt++) {
        const int col = nt * 8 + (lane & 3) * 2;
        {
            __half2 hp = __floats2half2_rn(o[nt][0] * inv0, o[nt][1] * inv0);
            *(__half2*)(Oatt + base0 + col) = hp;
        }
        {
            __half2 hp = __floats2half2_rn(o[nt][2] * inv1, o[nt][3] * inv1);
            *(__half2*)(Oatt + base1 + col) = hp;
        }
    }
}

// ---------------- launch -----------------------------------------------------
extern "C" void kernel_launch(void* const* d_in, const int* in_sizes, int n_in,
                              void* d_out, int out_size)
{
    const float* x  = (const float*)d_in[0];
    float* out = (float*)d_out;

    void *pq, *pk, *pv, *pxh, *pwh, *patt, *prope;
    cudaGetSymbolAddress(&pq,  g_q);
    cudaGetSymbolAddress(&pk,  g_k);
    cudaGetSymbolAddress(&pv,  g_v);
    cudaGetSymbolAddress(&pxh, g_xh);
    cudaGetSymbolAddress(&pwh, g_wh);
    cudaGetSymbolAddress(&patt, g_att);
    cudaGetSymbolAddress(&prope, g_rope);

    cudaFuncSetAttribute(gemm_mma<1>, cudaFuncAttributeMaxDynamicSharedMemorySize, GSMEM);
    cudaFuncSetAttribute(gemm_mma<0>, cudaFuncAttributeMaxDynamicSharedMemorySize, GSMEM);
    cudaFuncSetAttribute(flash_mma, cudaFuncAttributeMaxDynamicSharedMemorySize, FSMEM);

    __half* xh = (__half*)pxh;
    __half* wh = (__half*)pwh;

    // fused fp32->fp16 converts + RoPE table (one launch)
    split_all<<<(NCVT + NROPE + 255) / 256, 256>>>(
        x, (const float*)d_in[1], (const float*)d_in[2],
        (const float*)d_in[3], (const float*)d_in[4],
        xh, wh, (float2*)prope);

    // fused QKV projection -> plain fp16 [B,H,S,hd]
    dim3 qkvgrid(3 * D_ / 128, MTOT / 128);   // (24, 32)
    gemm_mma<1><<<qkvgrid, 256, GSMEM>>>(xh, wh, nullptr,
        (__half*)pq, (__half*)pk, (__half*)pv);

    // tensor-core causal flash attention -> plain fp16 [B,S,D]
    dim3 agrid(S_ / 64, B_ * H_);        // (32, 32), 2 CTAs/SM
    flash_mma<<<agrid, 128, FSMEM>>>((const __half*)pq, (const __half*)pk,
                                     (const __half*)pv, (__half*)patt);

    // output projection -> d_out (fp32)
    dim3 ogrid(D_ / 128, MTOT / 128);    // (8, 32)
    gemm_mma<0><<<ogrid, 256, GSMEM>>>((const __half*)patt,
                                       wh + 3*(size_t)D_*D_,
                                       out, nullptr, nullptr, nullptr);
}